// round 14
// baseline (speedup 1.0000x reference)
#include <cuda_runtime.h>

// ---------------------------------------------------------------------------
// SparseUNet, CHW layout. Convs: smem stencil-GEMM, double-buffered cp.async
// staging of inputs+weights, per-layer CG (2/4/8), rolled cg loop (I$),
// co-group-major grid. tconv: 8 co/thread. Pools: 4 out/thread + fused mask.
// ---------------------------------------------------------------------------

#define NB 2
#define PX 1024      // pixels per conv block
#define CO 16        // output channels per conv block

typedef unsigned long long u64;

__device__ __forceinline__ u64 pk2(float lo, float hi) {
    u64 r; asm("mov.b64 %0,{%1,%2};" : "=l"(r) : "f"(lo), "f"(hi)); return r;
}
__device__ __forceinline__ void upk2(u64 v, float& lo, float& hi) {
    asm("mov.b64 {%0,%1},%2;" : "=f"(lo), "=f"(hi) : "l"(v));
}
__device__ __forceinline__ void ffma2(u64& d, u64 a, u64 b) {
    asm("fma.rn.f32x2 %0,%1,%2,%0;" : "+l"(d) : "l"(a), "l"(b));
}
__device__ __forceinline__ void cpa16(unsigned dst, const float* src, bool ok) {
    int sz = ok ? 16 : 0;
    asm volatile("cp.async.cg.shared.global [%0], [%1], 16, %2;"
                 :: "r"(dst), "l"(src), "r"(sz));
}
__device__ __forceinline__ void cpa_commit() {
    asm volatile("cp.async.commit_group;");
}
template <int N> __device__ __forceinline__ void cpa_wait() {
    asm volatile("cp.async.wait_group %0;" :: "n"(N));
}

// ---- scratch (device globals; allocations forbidden) ----------------------
__device__ float g_xm[NB * 1024 * 1024];
__device__ float g_c1[NB * 16 * 1024 * 1024];
__device__ float g_p1[NB * 16 * 512 * 512];
__device__ float g_c2[NB * 32 * 512 * 512];
__device__ float g_p2[NB * 32 * 256 * 256];
__device__ float g_c3[NB * 64 * 256 * 256];
__device__ float g_p3[NB * 64 * 128 * 128];
__device__ float g_c4[NB * 128 * 128 * 128];
__device__ float g_p4[NB * 128 * 64 * 64];
__device__ float g_br[NB * 256 * 64 * 64];
__device__ float g_u4[NB * 128 * 128 * 128];
__device__ float g_r4[NB * 128 * 128 * 128];
__device__ float g_u3[NB * 64 * 256 * 256];
__device__ float g_r3[NB * 64 * 256 * 256];
__device__ float g_u2[NB * 32 * 512 * 512];
__device__ float g_r2[NB * 32 * 512 * 512];
__device__ float g_u1[NB * 16 * 1024 * 1024];
__device__ float g_r1[NB * 16 * 1024 * 1024];

__device__ unsigned char g_m0[NB * 1024 * 1024];
__device__ unsigned char g_m1[NB * 512 * 512];
__device__ unsigned char g_m2[NB * 256 * 256];
__device__ unsigned char g_m3[NB * 128 * 128];
__device__ unsigned char g_m4[NB * 64 * 64];
__device__ unsigned char g_mc4[NB * 128 * 128];
__device__ unsigned char g_mc3[NB * 256 * 256];
__device__ unsigned char g_mc2[NB * 512 * 512];
__device__ unsigned char g_mc1[NB * 1024 * 1024];

// ---------------------------------------------------------------------------
__global__ void k_init4(const float* __restrict__ x, const int* __restrict__ m,
                        float* __restrict__ xm, unsigned char* __restrict__ m0, int n4) {
    int i = blockIdx.x * blockDim.x + threadIdx.x;
    if (i >= n4) return;
    float4 xv = *reinterpret_cast<const float4*>(x + 4 * (long long)i);
    int4 mv = *reinterpret_cast<const int4*>(m + 4 * (long long)i);
    uchar4 mo;
    mo.x = mv.x != 0; mo.y = mv.y != 0; mo.z = mv.z != 0; mo.w = mv.w != 0;
    float4 o;
    o.x = mo.x ? xv.x : 0.0f;
    o.y = mo.y ? xv.y : 0.0f;
    o.z = mo.z ? xv.z : 0.0f;
    o.w = mo.w ? xv.w : 0.0f;
    *reinterpret_cast<float4*>(xm + 4 * (long long)i) = o;
    *reinterpret_cast<uchar4*>(m0 + 4 * (long long)i) = mo;
}

// ---------------------------------------------------------------------------
// smem-staged 3x3 conv, double-buffered cp.async staging, CGT channels/chunk.
// Grid: (co_groups, px_blocks, NB). Block: PX pixels x CO outputs, 256 thr.
// Dynamic smem: [2*CGT*144 weights][2*CGT*SLAB input], SLAB = PX + 2W + 8.
// ---------------------------------------------------------------------------
template <int CGT>
__global__ __launch_bounds__(256)
void conv3_smem(const float* __restrict__ A, const float* __restrict__ Bp,
                int Ca, int Cb,
                const float* __restrict__ w,
                const unsigned char* __restrict__ msk,
                float* __restrict__ out,
                int H, int W, int Cot) {
    extern __shared__ float sm[];
    const int HW = H * W;
    const int Ci = Ca + Cb;
    const int SLAB = PX + 2 * W + 8;
    const int WCH = CGT * 9 * CO;
    float* w_s = sm;                       // 2*WCH
    float* i_s = sm + 2 * WCH;             // 2*CGT*SLAB

    const int b = blockIdx.z;
    const int cobase = blockIdx.x * CO;
    const int tid = threadIdx.x;
    const int p0 = blockIdx.y * PX;

    // ---- per-pixel tap validity ----
    int pp[4];
    unsigned vmask[4];
#pragma unroll
    for (int p = 0; p < 4; p++) {
        pp[p] = p * 256 + tid;
        int gp = p0 + pp[p];
        int y = gp / W, x = gp % W;
        unsigned mm = 0;
#pragma unroll
        for (int ky = 0; ky < 3; ky++) {
            int yy = y + ky - 1;
            bool rok = (unsigned)yy < (unsigned)H;
#pragma unroll
            for (int kx = 0; kx < 3; kx++) {
                int xx = x + kx - 1;
                if (rok && (unsigned)xx < (unsigned)W)
                    mm |= 1u << (ky * 3 + kx);
            }
        }
        vmask[p] = mm;
    }

    u64 acc[4][CO / 2];
#pragma unroll
    for (int p = 0; p < 4; p++)
#pragma unroll
        for (int j = 0; j < CO / 2; j++) acc[p][j] = 0ull;

    const int NS4 = SLAB >> 2;
    const int g0 = p0 - W - 4;             // slab global start (multiple of 4)
    const int nk = Ci / CGT;

    auto stage = [&](int k, int buf) {
        const int c0 = k * CGT;
        for (int e = tid; e < CGT * 9 * 4; e += 256) {
            int f4 = e & 3;
            int tap = (e >> 2) % 9;
            int cg = e / 36;
            const float* src = w + ((long long)tap * Ci + c0 + cg) * Cot + cobase + 4 * f4;
            unsigned d = (unsigned)__cvta_generic_to_shared(
                w_s + buf * WCH + cg * (9 * CO) + tap * CO + 4 * f4);
            cpa16(d, src, true);
        }
        float* dstb = i_s + buf * (CGT * SLAB);
        for (int e = tid; e < CGT * NS4; e += 256) {
            int cg = e / NS4;
            int j = e - cg * NS4;
            int ci = c0 + cg;
            const float* plane = (ci < Ca)
                ? A + (long long)(b * Ca + ci) * HW
                : Bp + (long long)(b * Cb + (ci - Ca)) * HW;
            int g = g0 + (j << 2);
            bool ok = (g >= 0) && (g < HW);
            unsigned d = (unsigned)__cvta_generic_to_shared(dstb + cg * SLAB + (j << 2));
            cpa16(d, plane + (ok ? g : 0), ok);
        }
    };

    stage(0, 0);
    cpa_commit();

    for (int k = 0; k < nk; k++) {
        if (k + 1 < nk) { stage(k + 1, (k + 1) & 1); cpa_commit(); cpa_wait<1>(); }
        else            { cpa_wait<0>(); }
        __syncthreads();

        const float* ibuf = i_s + (k & 1) * (CGT * SLAB);
        const float* wbuf = w_s + (k & 1) * WCH;
#pragma unroll 1
        for (int cg = 0; cg < CGT; cg++) {
            const float* s = ibuf + cg * SLAB + (W + 4);
            const float* wb = wbuf + cg * (9 * CO);
#pragma unroll
            for (int ky = 0; ky < 3; ky++) {
#pragma unroll
                for (int kx = 0; kx < 3; kx++) {
                    const int t = ky * 3 + kx;
                    const ulonglong2* wp =
                        reinterpret_cast<const ulonglong2*>(wb + t * CO);
                    ulonglong2 wa = wp[0];
                    ulonglong2 wc = wp[1];
                    ulonglong2 wd = wp[2];
                    ulonglong2 we = wp[3];
                    const int doff = (ky - 1) * W + (kx - 1);
#pragma unroll
                    for (int p = 0; p < 4; p++) {
                        float v = (vmask[p] & (1u << t)) ? s[pp[p] + doff] : 0.0f;
                        u64 vv = pk2(v, v);
                        ffma2(acc[p][0], vv, wa.x);
                        ffma2(acc[p][1], vv, wa.y);
                        ffma2(acc[p][2], vv, wc.x);
                        ffma2(acc[p][3], vv, wc.y);
                        ffma2(acc[p][4], vv, wd.x);
                        ffma2(acc[p][5], vv, wd.y);
                        ffma2(acc[p][6], vv, we.x);
                        ffma2(acc[p][7], vv, we.y);
                    }
                }
            }
        }
        __syncthreads();
    }

#pragma unroll
    for (int p = 0; p < 4; p++) {
        int gp = p0 + pp[p];
        bool on = msk[b * HW + gp] != 0;
#pragma unroll
        for (int j = 0; j < CO / 2; j++) {
            float lo, hi;
            upk2(acc[p][j], lo, hi);
            long long o0 = (long long)(b * Cot + cobase + 2 * j) * HW + gp;
            out[o0] = on ? lo : 0.0f;
            out[o0 + HW] = on ? hi : 0.0f;
        }
    }
}

// ---------------------------------------------------------------------------
// ds1 conv: Ci=1, Co=16, W=H=1024.
// ---------------------------------------------------------------------------
__global__ __launch_bounds__(256)
void conv3_c1(const float* __restrict__ A,
              const float* __restrict__ w,
              const unsigned char* __restrict__ msk,
              float* __restrict__ out) {
    const int W = 1024, H = 1024, HW = W * H;
    const int SLAB = PX + 2 * W + 8;
    __shared__ float s_in[PX + 2 * 1024 + 8];
    __shared__ float s_w[9 * CO];

    const int b = blockIdx.z;
    const int tid = threadIdx.x;
    const int p0 = blockIdx.x * PX;
    const int g0 = p0 - W - 4;

    if (tid < 9 * CO) {
        int co = tid & 15, tap = tid >> 4;
        s_w[tid] = w[tap * CO + co];
    }
    for (int e = tid; e < (SLAB >> 2); e += 256) {
        int g = g0 + (e << 2);
        float4 v = make_float4(0.f, 0.f, 0.f, 0.f);
        if (g >= 0 && g < HW)
            v = *reinterpret_cast<const float4*>(A + (long long)b * HW + g);
        *reinterpret_cast<float4*>(s_in + (e << 2)) = v;
    }
    __syncthreads();

    int pp[4];
    unsigned vmask[4];
#pragma unroll
    for (int p = 0; p < 4; p++) {
        pp[p] = p * 256 + tid;
        int gp = p0 + pp[p];
        int y = gp / W, x = gp % W;
        unsigned mm = 0;
#pragma unroll
        for (int ky = 0; ky < 3; ky++) {
            int yy = y + ky - 1;
            bool rok = (unsigned)yy < (unsigned)H;
#pragma unroll
            for (int kx = 0; kx < 3; kx++) {
                int xx = x + kx - 1;
                if (rok && (unsigned)xx < (unsigned)W)
                    mm |= 1u << (ky * 3 + kx);
            }
        }
        vmask[p] = mm;
    }

    u64 acc[4][CO / 2];
#pragma unroll
    for (int p = 0; p < 4; p++)
#pragma unroll
        for (int j = 0; j < CO / 2; j++) acc[p][j] = 0ull;

    const float* s = s_in + (W + 4);
#pragma unroll
    for (int ky = 0; ky < 3; ky++) {
#pragma unroll
        for (int kx = 0; kx < 3; kx++) {
            const int t = ky * 3 + kx;
            const ulonglong2* wp = reinterpret_cast<const ulonglong2*>(s_w + t * CO);
            ulonglong2 wa = wp[0], wc = wp[1], wd = wp[2], we = wp[3];
            const int doff = (ky - 1) * W + (kx - 1);
#pragma unroll
            for (int p = 0; p < 4; p++) {
                float v = (vmask[p] & (1u << t)) ? s[pp[p] + doff] : 0.0f;
                u64 vv = pk2(v, v);
                ffma2(acc[p][0], vv, wa.x);
                ffma2(acc[p][1], vv, wa.y);
                ffma2(acc[p][2], vv, wc.x);
                ffma2(acc[p][3], vv, wc.y);
                ffma2(acc[p][4], vv, wd.x);
                ffma2(acc[p][5], vv, wd.y);
                ffma2(acc[p][6], vv, we.x);
                ffma2(acc[p][7], vv, we.y);
            }
        }
    }

#pragma unroll
    for (int p = 0; p < 4; p++) {
        int gp = p0 + pp[p];
        bool on = msk[b * HW + gp] != 0;
#pragma unroll
        for (int j = 0; j < CO / 2; j++) {
            float lo, hi;
            upk2(acc[p][j], lo, hi);
            long long o0 = (long long)(b * CO + 2 * j) * HW + gp;
            out[o0] = on ? lo : 0.0f;
            out[o0 + HW] = on ? hi : 0.0f;
        }
    }
}

// ---------------------------------------------------------------------------
// 2x2 stride-2 masked max pool, 4 outputs/thread; fused occupancy-mask pool
// (threads with c==0 write mo).
// ---------------------------------------------------------------------------
__global__ void k_pool4(const float* __restrict__ in, const unsigned char* __restrict__ mi,
                        float* __restrict__ out, unsigned char* __restrict__ mo,
                        int B, int C, int Ho, int Wo) {
    const int Wo4 = Wo >> 2;
    long long n = (long long)B * C * Ho * Wo4;
    long long i = (long long)blockIdx.x * blockDim.x + threadIdx.x;
    if (i >= n) return;
    int x4 = (int)(i % Wo4); long long t = i / Wo4;
    int yo = (int)(t % Ho); t /= Ho;
    int c = (int)(t % C);
    int b = (int)(t / C);
    int Wi = Wo * 2, Hi = Ho * 2;

    long long mrow = (long long)(b * Hi + 2 * yo) * Wi + 8 * x4;
    u64 ma = *reinterpret_cast<const u64*>(mi + mrow);
    u64 mb = *reinterpret_cast<const u64*>(mi + mrow + Wi);
    const float* ip = in + ((long long)((b * C + c) * Hi + 2 * yo) * Wi + 8 * x4);
    float4 a0 = *reinterpret_cast<const float4*>(ip);
    float4 a1 = *reinterpret_cast<const float4*>(ip + 4);
    float4 b0 = *reinterpret_cast<const float4*>(ip + Wi);
    float4 b1 = *reinterpret_cast<const float4*>(ip + Wi + 4);
    float va[8] = {a0.x, a0.y, a0.z, a0.w, a1.x, a1.y, a1.z, a1.w};
    float vb[8] = {b0.x, b0.y, b0.z, b0.w, b1.x, b1.y, b1.z, b1.w};

    float o[4];
    unsigned char mq[4];
#pragma unroll
    for (int j = 0; j < 4; j++) {
        int k0 = 2 * j, k1 = 2 * j + 1;
        float best = -3.4e38f; int any = 0;
        if ((ma >> (8 * k0)) & 0xff) { best = fmaxf(best, va[k0]); any = 1; }
        if ((ma >> (8 * k1)) & 0xff) { best = fmaxf(best, va[k1]); any = 1; }
        if ((mb >> (8 * k0)) & 0xff) { best = fmaxf(best, vb[k0]); any = 1; }
        if ((mb >> (8 * k1)) & 0xff) { best = fmaxf(best, vb[k1]); any = 1; }
        o[j] = any ? best : 0.0f;
        mq[j] = (unsigned char)any;
    }
    *reinterpret_cast<float4*>(out + (long long)((b * C + c) * Ho + yo) * Wo + 4 * x4) =
        make_float4(o[0], o[1], o[2], o[3]);
    if (c == 0)
        *reinterpret_cast<uchar4*>(mo + (long long)(b * Ho + yo) * Wo + 4 * x4) =
            make_uchar4(mq[0], mq[1], mq[2], mq[3]);
}

// mc: 4 px per thread
__global__ void k_mc4(const unsigned char* __restrict__ mcoarse,
                      const unsigned char* __restrict__ mfine,
                      unsigned char* __restrict__ mc, int B, int H, int W) {
    int n4 = B * H * W / 4;
    int i = blockIdx.x * blockDim.x + threadIdx.x;
    if (i >= n4) return;
    int px = 4 * i;
    int x = px % W; int t = px / W;
    int y = t % H; int b = t / H;
    uchar4 mf = *reinterpret_cast<const uchar4*>(mfine + px);
    const unsigned char* mcrow = mcoarse + (b * (H / 2) + (y >> 1)) * (W / 2) + (x >> 1);
    unsigned char c0 = mcrow[0], c1 = mcrow[1];
    uchar4 o;
    o.x = (mf.x | c0) ? 1 : 0;
    o.y = (mf.y | c0) ? 1 : 0;
    o.z = (mf.z | c1) ? 1 : 0;
    o.w = (mf.w | c1) ? 1 : 0;
    *reinterpret_cast<uchar4*>(mc + px) = o;
}

// ---------------------------------------------------------------------------
// kernel-2 stride-2 tconv, CHW; 2 input px x 8 co per thread; weights in smem.
// Grid: (px_blocks, Co/8, NB).
// ---------------------------------------------------------------------------
__global__ __launch_bounds__(256)
void tconv_chw(const float* __restrict__ in, const float* __restrict__ w,
               float* __restrict__ out, int Hi, int Wi, int Ci, int Co) {
    __shared__ float s_w[256 * 32];        // max Ci=256: 32KB
    const int HWi = Hi * Wi;
    const int HWo = HWi * 4;
    const int Wo = Wi * 2;
    const int b = blockIdx.z;
    const int cobase = blockIdx.y * 8;
    const int tid = threadIdx.x;

    // s_w[ci*32 + dt*8 + j] = w[(dt*Ci + ci)*Co + cobase + j]
    for (int e = tid; e < Ci * 32; e += 256) {
        int j = e & 7;
        int dt = (e >> 3) & 3;
        int ci = e >> 5;
        s_w[ci * 32 + dt * 8 + j] = w[((long long)dt * Ci + ci) * Co + cobase + j];
    }
    __syncthreads();

    int p0 = blockIdx.x * 512 + tid;
    int p1 = p0 + 256;
    bool v0 = p0 < HWi, v1 = p1 < HWi;

    u64 acc[2][4][4];
#pragma unroll
    for (int q = 0; q < 2; q++)
#pragma unroll
        for (int dt = 0; dt < 4; dt++)
#pragma unroll
            for (int j = 0; j < 4; j++) acc[q][dt][j] = 0ull;

    for (int ci = 0; ci < Ci; ci++) {
        const ulonglong2* wr = reinterpret_cast<const ulonglong2*>(s_w + ci * 32);
        const float* ip = in + (long long)(b * Ci + ci) * HWi;
        float x0 = v0 ? __ldg(ip + p0) : 0.0f;
        float x1 = v1 ? __ldg(ip + p1) : 0.0f;
        u64 xx0 = pk2(x0, x0), xx1 = pk2(x1, x1);
#pragma unroll
        for (int dt = 0; dt < 4; dt++) {
            ulonglong2 wlo = wr[2 * dt];
            ulonglong2 whi = wr[2 * dt + 1];
            ffma2(acc[0][dt][0], xx0, wlo.x); ffma2(acc[0][dt][1], xx0, wlo.y);
            ffma2(acc[0][dt][2], xx0, whi.x); ffma2(acc[0][dt][3], xx0, whi.y);
            ffma2(acc[1][dt][0], xx1, wlo.x); ffma2(acc[1][dt][1], xx1, wlo.y);
            ffma2(acc[1][dt][2], xx1, whi.x); ffma2(acc[1][dt][3], xx1, whi.y);
        }
    }

    int ps[2] = {p0, p1};
    bool vs[2] = {v0, v1};
#pragma unroll
    for (int q = 0; q < 2; q++) {
        if (!vs[q]) continue;
        int y = ps[q] / Wi, x = ps[q] % Wi;
        long long obase = (long long)(b * Co + cobase) * HWo;
#pragma unroll
        for (int dt = 0; dt < 4; dt++) {
            int yo = 2 * y + (dt >> 1);
            int xo = 2 * x + (dt & 1);
            long long oo = obase + (long long)yo * Wo + xo;
#pragma unroll
            for (int j = 0; j < 4; j++) {
                float lo, hi;
                upk2(acc[q][dt][j], lo, hi);
                out[oo + (long long)(2 * j) * HWo] = lo;
                out[oo + (long long)(2 * j + 1) * HWo] = hi;
            }
        }
    }
}

// final 1x1 conv 16->3, CHW in, NHWC out
__global__ void k_out1x1_chw(const float* __restrict__ in, const float* __restrict__ w,
                             const unsigned char* __restrict__ msk,
                             float* __restrict__ out, int HW) {
    int n = NB * HW;
    int i = blockIdx.x * blockDim.x + threadIdx.x;
    if (i >= n) return;
    long long o = (long long)i * 3;
    if (!msk[i]) { out[o] = 0.0f; out[o + 1] = 0.0f; out[o + 2] = 0.0f; return; }
    int b = i / HW, pix = i % HW;
    float a0 = 0.0f, a1 = 0.0f, a2 = 0.0f;
#pragma unroll
    for (int c = 0; c < 16; c++) {
        float v = __ldg(in + (long long)(b * 16 + c) * HW + pix);
        a0 = fmaf(v, w[c * 3 + 0], a0);
        a1 = fmaf(v, w[c * 3 + 1], a1);
        a2 = fmaf(v, w[c * 3 + 2], a2);
    }
    out[o] = a0; out[o + 1] = a1; out[o + 2] = a2;
}

// CHW [B,32,HW] -> NHWC [B,HW,32]
__global__ void k_tr_c2(const float* __restrict__ in, float* __restrict__ outp, int HW) {
    __shared__ float t[32][33];
    int b = blockIdx.y;
    int px0 = blockIdx.x * 32;
    int tx = threadIdx.x, ty = threadIdx.y;
#pragma unroll
    for (int k = 0; k < 4; k++) {
        int c = ty + k * 8;
        t[c][tx] = in[(long long)(b * 32 + c) * HW + px0 + tx];
    }
    __syncthreads();
#pragma unroll
    for (int k = 0; k < 4; k++) {
        int pl = ty + k * 8;
        outp[((long long)b * HW + px0 + pl) * 32 + tx] = t[tx][pl];
    }
}

// ---------------------------------------------------------------------------
static inline unsigned grid_for(long long n) { return (unsigned)((n + 255) / 256); }

static inline size_t conv_smem_bytes(int W, int cgt) {
    return (size_t)(2 * cgt * 9 * CO + 2 * cgt * (PX + 2 * W + 8)) * sizeof(float);
}

extern "C" void kernel_launch(void* const* d_in, const int* in_sizes, int n_in,
                              void* d_out, int out_size) {
    (void)in_sizes; (void)n_in; (void)out_size;

    const float* x      = (const float*)d_in[0];
    const int*   mask   = (const int*)d_in[1];
    const float* w_ds1  = (const float*)d_in[2];
    const float* w_ds2  = (const float*)d_in[3];
    const float* w_ds3  = (const float*)d_in[4];
    const float* w_ds4  = (const float*)d_in[5];
    const float* w_brdg = (const float*)d_in[6];
    const float* wt4    = (const float*)d_in[7];
    const float* w_us4  = (const float*)d_in[8];
    const float* wt3    = (const float*)d_in[9];
    const float* w_us3  = (const float*)d_in[10];
    const float* wt2    = (const float*)d_in[11];
    const float* w_us2  = (const float*)d_in[12];
    const float* wt1    = (const float*)d_in[13];
    const float* w_us1  = (const float*)d_in[14];
    const float* w_out  = (const float*)d_in[15];

    float* out_final = (float*)d_out;                                    // [2,1024,1024,3]
    float* c2_out    = (float*)d_out + (long long)NB * 1024 * 1024 * 3;  // [2,512,512,32]

    float *xm, *c1, *p1, *c2, *p2, *c3, *p3, *c4, *p4, *br, *u4, *r4, *u3, *r3, *u2, *r2, *u1, *r1;
    unsigned char *m0, *m1, *m2, *m3, *m4, *mc4, *mc3, *mc2, *mc1;
    cudaGetSymbolAddress((void**)&xm, g_xm);
    cudaGetSymbolAddress((void**)&c1, g_c1);
    cudaGetSymbolAddress((void**)&p1, g_p1);
    cudaGetSymbolAddress((void**)&c2, g_c2);
    cudaGetSymbolAddress((void**)&p2, g_p2);
    cudaGetSymbolAddress((void**)&c3, g_c3);
    cudaGetSymbolAddress((void**)&p3, g_p3);
    cudaGetSymbolAddress((void**)&c4, g_c4);
    cudaGetSymbolAddress((void**)&p4, g_p4);
    cudaGetSymbolAddress((void**)&br, g_br);
    cudaGetSymbolAddress((void**)&u4, g_u4);
    cudaGetSymbolAddress((void**)&r4, g_r4);
    cudaGetSymbolAddress((void**)&u3, g_u3);
    cudaGetSymbolAddress((void**)&r3, g_r3);
    cudaGetSymbolAddress((void**)&u2, g_u2);
    cudaGetSymbolAddress((void**)&r2, g_r2);
    cudaGetSymbolAddress((void**)&u1, g_u1);
    cudaGetSymbolAddress((void**)&r1, g_r1);
    cudaGetSymbolAddress((void**)&m0, g_m0);
    cudaGetSymbolAddress((void**)&m1, g_m1);
    cudaGetSymbolAddress((void**)&m2, g_m2);
    cudaGetSymbolAddress((void**)&m3, g_m3);
    cudaGetSymbolAddress((void**)&m4, g_m4);
    cudaGetSymbolAddress((void**)&mc4, g_mc4);
    cudaGetSymbolAddress((void**)&mc3, g_mc3);
    cudaGetSymbolAddress((void**)&mc2, g_mc2);
    cudaGetSymbolAddress((void**)&mc1, g_mc1);

    cudaFuncSetAttribute(conv3_smem<2>, cudaFuncAttributeMaxDynamicSharedMemorySize,
                         (int)conv_smem_bytes(1024, 2) + 256);
    cudaFuncSetAttribute(conv3_smem<4>, cudaFuncAttributeMaxDynamicSharedMemorySize,
                         (int)conv_smem_bytes(512, 4) + 256);
    cudaFuncSetAttribute(conv3_smem<8>, cudaFuncAttributeMaxDynamicSharedMemorySize,
                         (int)conv_smem_bytes(256, 8) + 256);

    const int TB = 256;
    long long n;

    n = (long long)NB * 1024 * 1024 / 4;
    k_init4<<<grid_for(n), TB>>>(x, mask, xm, m0, (int)n);

    // --- encoder ---
    conv3_c1<<<dim3(1024 * 1024 / PX, 1, NB), TB>>>(xm, w_ds1, m0, c1);

    n = (long long)NB * 16 * 512 * 512 / 4;
    k_pool4<<<grid_for(n), TB>>>(c1, m0, p1, m1, NB, 16, 512, 512);

    conv3_smem<4><<<dim3(2, 256, NB), TB, conv_smem_bytes(512, 4)>>>(
        p1, nullptr, 16, 0, w_ds2, m1, c2, 512, 512, 32);

    n = (long long)NB * 32 * 256 * 256 / 4;
    k_pool4<<<grid_for(n), TB>>>(c2, m1, p2, m2, NB, 32, 256, 256);

    conv3_smem<8><<<dim3(4, 64, NB), TB, conv_smem_bytes(256, 8)>>>(
        p2, nullptr, 32, 0, w_ds3, m2, c3, 256, 256, 64);

    n = (long long)NB * 64 * 128 * 128 / 4;
    k_pool4<<<grid_for(n), TB>>>(c3, m2, p3, m3, NB, 64, 128, 128);

    conv3_smem<8><<<dim3(8, 16, NB), TB, conv_smem_bytes(128, 8)>>>(
        p3, nullptr, 64, 0, w_ds4, m3, c4, 128, 128, 128);

    n = (long long)NB * 128 * 64 * 64 / 4;
    k_pool4<<<grid_for(n), TB>>>(c4, m3, p4, m4, NB, 128, 64, 64);

    // --- bridge ---
    conv3_smem<8><<<dim3(16, 4, NB), TB, conv_smem_bytes(64, 8)>>>(
        p4, nullptr, 128, 0, w_brdg, m4, br, 64, 64, 256);

    // --- decoder 4 ---
    tconv_chw<<<dim3(8, 16, NB), TB>>>(br, wt4, u4, 64, 64, 256, 128);
    n = (long long)NB * 128 * 128 / 4;
    k_mc4<<<grid_for(n), TB>>>(m4, m3, mc4, NB, 128, 128);
    conv3_smem<8><<<dim3(8, 16, NB), TB, conv_smem_bytes(128, 8)>>>(
        u4, c4, 128, 128, w_us4, mc4, r4, 128, 128, 128);

    // --- decoder 3 ---
    tconv_chw<<<dim3(32, 8, NB), TB>>>(r4, wt3, u3, 128, 128, 128, 64);
    n = (long long)NB * 256 * 256 / 4;
    k_mc4<<<grid_for(n), TB>>>(mc4, m2, mc3, NB, 256, 256);
    conv3_smem<8><<<dim3(4, 64, NB), TB, conv_smem_bytes(256, 8)>>>(
        u3, c3, 64, 64, w_us3, mc3, r3, 256, 256, 64);

    // --- decoder 2 ---
    tconv_chw<<<dim3(128, 4, NB), TB>>>(r3, wt2, u2, 256, 256, 64, 32);
    n = (long long)NB * 512 * 512 / 4;
    k_mc4<<<grid_for(n), TB>>>(mc3, m1, mc2, NB, 512, 512);
    conv3_smem<4><<<dim3(2, 256, NB), TB, conv_smem_bytes(512, 4)>>>(
        u2, c2, 32, 32, w_us2, mc2, r2, 512, 512, 32);

    // --- decoder 1 ---
    tconv_chw<<<dim3(512, 2, NB), TB>>>(r2, wt1, u1, 512, 512, 32, 16);
    n = (long long)NB * 1024 * 1024 / 4;
    k_mc4<<<grid_for(n), TB>>>(mc2, m0, mc1, NB, 1024, 1024);
    conv3_smem<2><<<dim3(1, 1024, NB), TB, conv_smem_bytes(1024, 2)>>>(
        u1, c1, 16, 16, w_us1, mc1, r1, 1024, 1024, 16);

    // --- outputs ---
    n = (long long)NB * 1024 * 1024;
    k_out1x1_chw<<<grid_for(n), TB>>>(r1, w_out, mc1, out_final, 1024 * 1024);

    k_tr_c2<<<dim3(512 * 512 / 32, NB), dim3(32, 8)>>>(c2, c2_out, 512 * 512);
}

// round 15
// speedup vs baseline: 1.1596x; 1.1596x over previous
#include <cuda_runtime.h>

// ---------------------------------------------------------------------------
// SparseUNet, CHW layout. Convs: smem stencil-GEMM, double-buffered cp.async
// staging of inputs+weights, CG=4, fully unrolled body, launch_bounds(256,2)
// to pin 2 CTAs/SM. Pools: 4 out/thread + fused mask. tconv: 8 co/thread.
// ---------------------------------------------------------------------------

#define NB 2
#define PX 1024      // pixels per conv block
#define CO 16        // output channels per conv block
#define CG 4         // input channels staged per chunk
#define WCHUNK (CG * 9 * CO)   // 576 floats

typedef unsigned long long u64;

__device__ __forceinline__ u64 pk2(float lo, float hi) {
    u64 r; asm("mov.b64 %0,{%1,%2};" : "=l"(r) : "f"(lo), "f"(hi)); return r;
}
__device__ __forceinline__ void upk2(u64 v, float& lo, float& hi) {
    asm("mov.b64 {%0,%1},%2;" : "=f"(lo), "=f"(hi) : "l"(v));
}
__device__ __forceinline__ void ffma2(u64& d, u64 a, u64 b) {
    asm("fma.rn.f32x2 %0,%1,%2,%0;" : "+l"(d) : "l"(a), "l"(b));
}
__device__ __forceinline__ void cpa16(unsigned dst, const float* src, bool ok) {
    int sz = ok ? 16 : 0;
    asm volatile("cp.async.cg.shared.global [%0], [%1], 16, %2;"
                 :: "r"(dst), "l"(src), "r"(sz));
}
__device__ __forceinline__ void cpa_commit() {
    asm volatile("cp.async.commit_group;");
}
template <int N> __device__ __forceinline__ void cpa_wait() {
    asm volatile("cp.async.wait_group %0;" :: "n"(N));
}

// ---- scratch (device globals; allocations forbidden) ----------------------
__device__ float g_xm[NB * 1024 * 1024];
__device__ float g_c1[NB * 16 * 1024 * 1024];
__device__ float g_p1[NB * 16 * 512 * 512];
__device__ float g_c2[NB * 32 * 512 * 512];
__device__ float g_p2[NB * 32 * 256 * 256];
__device__ float g_c3[NB * 64 * 256 * 256];
__device__ float g_p3[NB * 64 * 128 * 128];
__device__ float g_c4[NB * 128 * 128 * 128];
__device__ float g_p4[NB * 128 * 64 * 64];
__device__ float g_br[NB * 256 * 64 * 64];
__device__ float g_u4[NB * 128 * 128 * 128];
__device__ float g_r4[NB * 128 * 128 * 128];
__device__ float g_u3[NB * 64 * 256 * 256];
__device__ float g_r3[NB * 64 * 256 * 256];
__device__ float g_u2[NB * 32 * 512 * 512];
__device__ float g_r2[NB * 32 * 512 * 512];
__device__ float g_u1[NB * 16 * 1024 * 1024];
__device__ float g_r1[NB * 16 * 1024 * 1024];

__device__ unsigned char g_m0[NB * 1024 * 1024];
__device__ unsigned char g_m1[NB * 512 * 512];
__device__ unsigned char g_m2[NB * 256 * 256];
__device__ unsigned char g_m3[NB * 128 * 128];
__device__ unsigned char g_m4[NB * 64 * 64];
__device__ unsigned char g_mc4[NB * 128 * 128];
__device__ unsigned char g_mc3[NB * 256 * 256];
__device__ unsigned char g_mc2[NB * 512 * 512];
__device__ unsigned char g_mc1[NB * 1024 * 1024];

// ---------------------------------------------------------------------------
__global__ void k_init4(const float* __restrict__ x, const int* __restrict__ m,
                        float* __restrict__ xm, unsigned char* __restrict__ m0, int n4) {
    int i = blockIdx.x * blockDim.x + threadIdx.x;
    if (i >= n4) return;
    float4 xv = *reinterpret_cast<const float4*>(x + 4 * (long long)i);
    int4 mv = *reinterpret_cast<const int4*>(m + 4 * (long long)i);
    uchar4 mo;
    mo.x = mv.x != 0; mo.y = mv.y != 0; mo.z = mv.z != 0; mo.w = mv.w != 0;
    float4 o;
    o.x = mo.x ? xv.x : 0.0f;
    o.y = mo.y ? xv.y : 0.0f;
    o.z = mo.z ? xv.z : 0.0f;
    o.w = mo.w ? xv.w : 0.0f;
    *reinterpret_cast<float4*>(xm + 4 * (long long)i) = o;
    *reinterpret_cast<uchar4*>(m0 + 4 * (long long)i) = mo;
}

// ---------------------------------------------------------------------------
// smem-staged 3x3 conv, double-buffered cp.async staging of inputs + weights.
// Grid: (px_blocks, co_groups, NB). Block: PX pixels x CO outputs, 256 thr.
// Dynamic smem: [2*WCHUNK weights][2*CG*SLAB input], SLAB = PX + 2W + 8.
// launch_bounds(256, 2): cap regs at 128 -> 2 CTAs/SM.
// ---------------------------------------------------------------------------
__global__ __launch_bounds__(256, 2)
void conv3_smem(const float* __restrict__ A, const float* __restrict__ Bp,
                int Ca, int Cb,
                const float* __restrict__ w,
                const unsigned char* __restrict__ msk,
                float* __restrict__ out,
                int H, int W, int Cot) {
    extern __shared__ float sm[];
    const int HW = H * W;
    const int Ci = Ca + Cb;
    const int SLAB = PX + 2 * W + 8;
    float* w_s = sm;                       // 2*WCHUNK
    float* i_s = sm + 2 * WCHUNK;          // 2*CG*SLAB

    const int b = blockIdx.z;
    const int cobase = blockIdx.y * CO;
    const int tid = threadIdx.x;
    const int p0 = blockIdx.x * PX;

    // ---- per-pixel tap validity ----
    int pp[4];
    unsigned vmask[4];
#pragma unroll
    for (int p = 0; p < 4; p++) {
        pp[p] = p * 256 + tid;
        int gp = p0 + pp[p];
        int y = gp / W, x = gp % W;
        unsigned mm = 0;
#pragma unroll
        for (int ky = 0; ky < 3; ky++) {
            int yy = y + ky - 1;
            bool rok = (unsigned)yy < (unsigned)H;
#pragma unroll
            for (int kx = 0; kx < 3; kx++) {
                int xx = x + kx - 1;
                if (rok && (unsigned)xx < (unsigned)W)
                    mm |= 1u << (ky * 3 + kx);
            }
        }
        vmask[p] = mm;
    }

    u64 acc[4][CO / 2];
#pragma unroll
    for (int p = 0; p < 4; p++)
#pragma unroll
        for (int j = 0; j < CO / 2; j++) acc[p][j] = 0ull;

    const int NS4 = SLAB >> 2;
    const int g0 = p0 - W - 4;             // slab global start (multiple of 4)
    const int nk = Ci / CG;

    auto stage = [&](int k, int buf) {
        const int c0 = k * CG;
        for (int e = tid; e < CG * 9 * 4; e += 256) {
            int f4 = e & 3;
            int tap = (e >> 2) % 9;
            int cg = e / 36;
            const float* src = w + ((long long)tap * Ci + c0 + cg) * Cot + cobase + 4 * f4;
            unsigned d = (unsigned)__cvta_generic_to_shared(
                w_s + buf * WCHUNK + cg * (9 * CO) + tap * CO + 4 * f4);
            cpa16(d, src, true);
        }
        float* dstb = i_s + buf * (CG * SLAB);
        for (int e = tid; e < CG * NS4; e += 256) {
            int cg = e / NS4;
            int j = e - cg * NS4;
            int ci = c0 + cg;
            const float* plane = (ci < Ca)
                ? A + (long long)(b * Ca + ci) * HW
                : Bp + (long long)(b * Cb + (ci - Ca)) * HW;
            int g = g0 + (j << 2);
            bool ok = (g >= 0) && (g < HW);
            unsigned d = (unsigned)__cvta_generic_to_shared(dstb + cg * SLAB + (j << 2));
            cpa16(d, plane + (ok ? g : 0), ok);
        }
    };

    stage(0, 0);
    cpa_commit();

    for (int k = 0; k < nk; k++) {
        if (k + 1 < nk) { stage(k + 1, (k + 1) & 1); cpa_commit(); cpa_wait<1>(); }
        else            { cpa_wait<0>(); }
        __syncthreads();

        const float* ibuf = i_s + (k & 1) * (CG * SLAB);
        const float* wbuf = w_s + (k & 1) * WCHUNK;
#pragma unroll
        for (int cg = 0; cg < CG; cg++) {
            const float* s = ibuf + cg * SLAB + (W + 4);
            const float* wb = wbuf + cg * (9 * CO);
#pragma unroll
            for (int ky = 0; ky < 3; ky++) {
#pragma unroll
                for (int kx = 0; kx < 3; kx++) {
                    const int t = ky * 3 + kx;
                    const ulonglong2* wp =
                        reinterpret_cast<const ulonglong2*>(wb + t * CO);
                    ulonglong2 wa = wp[0];
                    ulonglong2 wc = wp[1];
                    ulonglong2 wd = wp[2];
                    ulonglong2 we = wp[3];
                    const int doff = (ky - 1) * W + (kx - 1);
#pragma unroll
                    for (int p = 0; p < 4; p++) {
                        float v = (vmask[p] & (1u << t)) ? s[pp[p] + doff] : 0.0f;
                        u64 vv = pk2(v, v);
                        ffma2(acc[p][0], vv, wa.x);
                        ffma2(acc[p][1], vv, wa.y);
                        ffma2(acc[p][2], vv, wc.x);
                        ffma2(acc[p][3], vv, wc.y);
                        ffma2(acc[p][4], vv, wd.x);
                        ffma2(acc[p][5], vv, wd.y);
                        ffma2(acc[p][6], vv, we.x);
                        ffma2(acc[p][7], vv, we.y);
                    }
                }
            }
        }
        __syncthreads();
    }

#pragma unroll
    for (int p = 0; p < 4; p++) {
        int gp = p0 + pp[p];
        bool on = msk[b * HW + gp] != 0;
#pragma unroll
        for (int j = 0; j < CO / 2; j++) {
            float lo, hi;
            upk2(acc[p][j], lo, hi);
            long long o0 = (long long)(b * Cot + cobase + 2 * j) * HW + gp;
            out[o0] = on ? lo : 0.0f;
            out[o0 + HW] = on ? hi : 0.0f;
        }
    }
}

// ---------------------------------------------------------------------------
// ds1 conv: Ci=1, Co=16, W=H=1024.
// ---------------------------------------------------------------------------
__global__ __launch_bounds__(256)
void conv3_c1(const float* __restrict__ A,
              const float* __restrict__ w,
              const unsigned char* __restrict__ msk,
              float* __restrict__ out) {
    const int W = 1024, H = 1024, HW = W * H;
    const int SLAB = PX + 2 * W + 8;
    __shared__ float s_in[PX + 2 * 1024 + 8];
    __shared__ float s_w[9 * CO];

    const int b = blockIdx.z;
    const int tid = threadIdx.x;
    const int p0 = blockIdx.x * PX;
    const int g0 = p0 - W - 4;

    if (tid < 9 * CO) {
        int co = tid & 15, tap = tid >> 4;
        s_w[tid] = w[tap * CO + co];
    }
    for (int e = tid; e < (SLAB >> 2); e += 256) {
        int g = g0 + (e << 2);
        float4 v = make_float4(0.f, 0.f, 0.f, 0.f);
        if (g >= 0 && g < HW)
            v = *reinterpret_cast<const float4*>(A + (long long)b * HW + g);
        *reinterpret_cast<float4*>(s_in + (e << 2)) = v;
    }
    __syncthreads();

    int pp[4];
    unsigned vmask[4];
#pragma unroll
    for (int p = 0; p < 4; p++) {
        pp[p] = p * 256 + tid;
        int gp = p0 + pp[p];
        int y = gp / W, x = gp % W;
        unsigned mm = 0;
#pragma unroll
        for (int ky = 0; ky < 3; ky++) {
            int yy = y + ky - 1;
            bool rok = (unsigned)yy < (unsigned)H;
#pragma unroll
            for (int kx = 0; kx < 3; kx++) {
                int xx = x + kx - 1;
                if (rok && (unsigned)xx < (unsigned)W)
                    mm |= 1u << (ky * 3 + kx);
            }
        }
        vmask[p] = mm;
    }

    u64 acc[4][CO / 2];
#pragma unroll
    for (int p = 0; p < 4; p++)
#pragma unroll
        for (int j = 0; j < CO / 2; j++) acc[p][j] = 0ull;

    const float* s = s_in + (W + 4);
#pragma unroll
    for (int ky = 0; ky < 3; ky++) {
#pragma unroll
        for (int kx = 0; kx < 3; kx++) {
            const int t = ky * 3 + kx;
            const ulonglong2* wp = reinterpret_cast<const ulonglong2*>(s_w + t * CO);
            ulonglong2 wa = wp[0], wc = wp[1], wd = wp[2], we = wp[3];
            const int doff = (ky - 1) * W + (kx - 1);
#pragma unroll
            for (int p = 0; p < 4; p++) {
                float v = (vmask[p] & (1u << t)) ? s[pp[p] + doff] : 0.0f;
                u64 vv = pk2(v, v);
                ffma2(acc[p][0], vv, wa.x);
                ffma2(acc[p][1], vv, wa.y);
                ffma2(acc[p][2], vv, wc.x);
                ffma2(acc[p][3], vv, wc.y);
                ffma2(acc[p][4], vv, wd.x);
                ffma2(acc[p][5], vv, wd.y);
                ffma2(acc[p][6], vv, we.x);
                ffma2(acc[p][7], vv, we.y);
            }
        }
    }

#pragma unroll
    for (int p = 0; p < 4; p++) {
        int gp = p0 + pp[p];
        bool on = msk[b * HW + gp] != 0;
#pragma unroll
        for (int j = 0; j < CO / 2; j++) {
            float lo, hi;
            upk2(acc[p][j], lo, hi);
            long long o0 = (long long)(b * CO + 2 * j) * HW + gp;
            out[o0] = on ? lo : 0.0f;
            out[o0 + HW] = on ? hi : 0.0f;
        }
    }
}

// ---------------------------------------------------------------------------
// 2x2 stride-2 masked max pool, 4 outputs/thread; fused mask pool (c==0).
// ---------------------------------------------------------------------------
__global__ void k_pool4(const float* __restrict__ in, const unsigned char* __restrict__ mi,
                        float* __restrict__ out, unsigned char* __restrict__ mo,
                        int B, int C, int Ho, int Wo) {
    const int Wo4 = Wo >> 2;
    long long n = (long long)B * C * Ho * Wo4;
    long long i = (long long)blockIdx.x * blockDim.x + threadIdx.x;
    if (i >= n) return;
    int x4 = (int)(i % Wo4); long long t = i / Wo4;
    int yo = (int)(t % Ho); t /= Ho;
    int c = (int)(t % C);
    int b = (int)(t / C);
    int Wi = Wo * 2, Hi = Ho * 2;

    long long mrow = (long long)(b * Hi + 2 * yo) * Wi + 8 * x4;
    u64 ma = *reinterpret_cast<const u64*>(mi + mrow);
    u64 mb = *reinterpret_cast<const u64*>(mi + mrow + Wi);
    const float* ip = in + ((long long)((b * C + c) * Hi + 2 * yo) * Wi + 8 * x4);
    float4 a0 = *reinterpret_cast<const float4*>(ip);
    float4 a1 = *reinterpret_cast<const float4*>(ip + 4);
    float4 b0 = *reinterpret_cast<const float4*>(ip + Wi);
    float4 b1 = *reinterpret_cast<const float4*>(ip + Wi + 4);
    float va[8] = {a0.x, a0.y, a0.z, a0.w, a1.x, a1.y, a1.z, a1.w};
    float vb[8] = {b0.x, b0.y, b0.z, b0.w, b1.x, b1.y, b1.z, b1.w};

    float o[4];
    unsigned char mq[4];
#pragma unroll
    for (int j = 0; j < 4; j++) {
        int k0 = 2 * j, k1 = 2 * j + 1;
        float best = -3.4e38f; int any = 0;
        if ((ma >> (8 * k0)) & 0xff) { best = fmaxf(best, va[k0]); any = 1; }
        if ((ma >> (8 * k1)) & 0xff) { best = fmaxf(best, va[k1]); any = 1; }
        if ((mb >> (8 * k0)) & 0xff) { best = fmaxf(best, vb[k0]); any = 1; }
        if ((mb >> (8 * k1)) & 0xff) { best = fmaxf(best, vb[k1]); any = 1; }
        o[j] = any ? best : 0.0f;
        mq[j] = (unsigned char)any;
    }
    *reinterpret_cast<float4*>(out + (long long)((b * C + c) * Ho + yo) * Wo + 4 * x4) =
        make_float4(o[0], o[1], o[2], o[3]);
    if (c == 0)
        *reinterpret_cast<uchar4*>(mo + (long long)(b * Ho + yo) * Wo + 4 * x4) =
            make_uchar4(mq[0], mq[1], mq[2], mq[3]);
}

// mc: 4 px per thread
__global__ void k_mc4(const unsigned char* __restrict__ mcoarse,
                      const unsigned char* __restrict__ mfine,
                      unsigned char* __restrict__ mc, int B, int H, int W) {
    int n4 = B * H * W / 4;
    int i = blockIdx.x * blockDim.x + threadIdx.x;
    if (i >= n4) return;
    int px = 4 * i;
    int x = px % W; int t = px / W;
    int y = t % H; int b = t / H;
    uchar4 mf = *reinterpret_cast<const uchar4*>(mfine + px);
    const unsigned char* mcrow = mcoarse + (b * (H / 2) + (y >> 1)) * (W / 2) + (x >> 1);
    unsigned char c0 = mcrow[0], c1 = mcrow[1];
    uchar4 o;
    o.x = (mf.x | c0) ? 1 : 0;
    o.y = (mf.y | c0) ? 1 : 0;
    o.z = (mf.z | c1) ? 1 : 0;
    o.w = (mf.w | c1) ? 1 : 0;
    *reinterpret_cast<uchar4*>(mc + px) = o;
}

// ---------------------------------------------------------------------------
// kernel-2 stride-2 tconv, CHW; 2 input px x 8 co per thread; weights in smem.
// ---------------------------------------------------------------------------
__global__ __launch_bounds__(256)
void tconv_chw(const float* __restrict__ in, const float* __restrict__ w,
               float* __restrict__ out, int Hi, int Wi, int Ci, int Co) {
    __shared__ float s_w[256 * 32];        // max Ci=256: 32KB
    const int HWi = Hi * Wi;
    const int HWo = HWi * 4;
    const int Wo = Wi * 2;
    const int b = blockIdx.z;
    const int cobase = blockIdx.y * 8;
    const int tid = threadIdx.x;

    for (int e = tid; e < Ci * 32; e += 256) {
        int j = e & 7;
        int dt = (e >> 3) & 3;
        int ci = e >> 5;
        s_w[ci * 32 + dt * 8 + j] = w[((long long)dt * Ci + ci) * Co + cobase + j];
    }
    __syncthreads();

    int p0 = blockIdx.x * 512 + tid;
    int p1 = p0 + 256;
    bool v0 = p0 < HWi, v1 = p1 < HWi;

    u64 acc[2][4][4];
#pragma unroll
    for (int q = 0; q < 2; q++)
#pragma unroll
        for (int dt = 0; dt < 4; dt++)
#pragma unroll
            for (int j = 0; j < 4; j++) acc[q][dt][j] = 0ull;

    for (int ci = 0; ci < Ci; ci++) {
        const ulonglong2* wr = reinterpret_cast<const ulonglong2*>(s_w + ci * 32);
        const float* ip = in + (long long)(b * Ci + ci) * HWi;
        float x0 = v0 ? __ldg(ip + p0) : 0.0f;
        float x1 = v1 ? __ldg(ip + p1) : 0.0f;
        u64 xx0 = pk2(x0, x0), xx1 = pk2(x1, x1);
#pragma unroll
        for (int dt = 0; dt < 4; dt++) {
            ulonglong2 wlo = wr[2 * dt];
            ulonglong2 whi = wr[2 * dt + 1];
            ffma2(acc[0][dt][0], xx0, wlo.x); ffma2(acc[0][dt][1], xx0, wlo.y);
            ffma2(acc[0][dt][2], xx0, whi.x); ffma2(acc[0][dt][3], xx0, whi.y);
            ffma2(acc[1][dt][0], xx1, wlo.x); ffma2(acc[1][dt][1], xx1, wlo.y);
            ffma2(acc[1][dt][2], xx1, whi.x); ffma2(acc[1][dt][3], xx1, whi.y);
        }
    }

    int ps[2] = {p0, p1};
    bool vs[2] = {v0, v1};
#pragma unroll
    for (int q = 0; q < 2; q++) {
        if (!vs[q]) continue;
        int y = ps[q] / Wi, x = ps[q] % Wi;
        long long obase = (long long)(b * Co + cobase) * HWo;
#pragma unroll
        for (int dt = 0; dt < 4; dt++) {
            int yo = 2 * y + (dt >> 1);
            int xo = 2 * x + (dt & 1);
            long long oo = obase + (long long)yo * Wo + xo;
#pragma unroll
            for (int j = 0; j < 4; j++) {
                float lo, hi;
                upk2(acc[q][dt][j], lo, hi);
                out[oo + (long long)(2 * j) * HWo] = lo;
                out[oo + (long long)(2 * j + 1) * HWo] = hi;
            }
        }
    }
}

// final 1x1 conv 16->3, CHW in, NHWC out
__global__ void k_out1x1_chw(const float* __restrict__ in, const float* __restrict__ w,
                             const unsigned char* __restrict__ msk,
                             float* __restrict__ out, int HW) {
    int n = NB * HW;
    int i = blockIdx.x * blockDim.x + threadIdx.x;
    if (i >= n) return;
    long long o = (long long)i * 3;
    if (!msk[i]) { out[o] = 0.0f; out[o + 1] = 0.0f; out[o + 2] = 0.0f; return; }
    int b = i / HW, pix = i % HW;
    float a0 = 0.0f, a1 = 0.0f, a2 = 0.0f;
#pragma unroll
    for (int c = 0; c < 16; c++) {
        float v = __ldg(in + (long long)(b * 16 + c) * HW + pix);
        a0 = fmaf(v, w[c * 3 + 0], a0);
        a1 = fmaf(v, w[c * 3 + 1], a1);
        a2 = fmaf(v, w[c * 3 + 2], a2);
    }
    out[o] = a0; out[o + 1] = a1; out[o + 2] = a2;
}

// CHW [B,32,HW] -> NHWC [B,HW,32]
__global__ void k_tr_c2(const float* __restrict__ in, float* __restrict__ outp, int HW) {
    __shared__ float t[32][33];
    int b = blockIdx.y;
    int px0 = blockIdx.x * 32;
    int tx = threadIdx.x, ty = threadIdx.y;
#pragma unroll
    for (int k = 0; k < 4; k++) {
        int c = ty + k * 8;
        t[c][tx] = in[(long long)(b * 32 + c) * HW + px0 + tx];
    }
    __syncthreads();
#pragma unroll
    for (int k = 0; k < 4; k++) {
        int pl = ty + k * 8;
        outp[((long long)b * HW + px0 + pl) * 32 + tx] = t[tx][pl];
    }
}

// ---------------------------------------------------------------------------
static inline unsigned grid_for(long long n) { return (unsigned)((n + 255) / 256); }

static inline size_t conv_smem_bytes(int W) {
    return (size_t)(2 * WCHUNK + 2 * CG * (PX + 2 * W + 8)) * sizeof(float);
}

extern "C" void kernel_launch(void* const* d_in, const int* in_sizes, int n_in,
                              void* d_out, int out_size) {
    (void)in_sizes; (void)n_in; (void)out_size;

    const float* x      = (const float*)d_in[0];
    const int*   mask   = (const int*)d_in[1];
    const float* w_ds1  = (const float*)d_in[2];
    const float* w_ds2  = (const float*)d_in[3];
    const float* w_ds3  = (const float*)d_in[4];
    const float* w_ds4  = (const float*)d_in[5];
    const float* w_brdg = (const float*)d_in[6];
    const float* wt4    = (const float*)d_in[7];
    const float* w_us4  = (const float*)d_in[8];
    const float* wt3    = (const float*)d_in[9];
    const float* w_us3  = (const float*)d_in[10];
    const float* wt2    = (const float*)d_in[11];
    const float* w_us2  = (const float*)d_in[12];
    const float* wt1    = (const float*)d_in[13];
    const float* w_us1  = (const float*)d_in[14];
    const float* w_out  = (const float*)d_in[15];

    float* out_final = (float*)d_out;                                    // [2,1024,1024,3]
    float* c2_out    = (float*)d_out + (long long)NB * 1024 * 1024 * 3;  // [2,512,512,32]

    float *xm, *c1, *p1, *c2, *p2, *c3, *p3, *c4, *p4, *br, *u4, *r4, *u3, *r3, *u2, *r2, *u1, *r1;
    unsigned char *m0, *m1, *m2, *m3, *m4, *mc4, *mc3, *mc2, *mc1;
    cudaGetSymbolAddress((void**)&xm, g_xm);
    cudaGetSymbolAddress((void**)&c1, g_c1);
    cudaGetSymbolAddress((void**)&p1, g_p1);
    cudaGetSymbolAddress((void**)&c2, g_c2);
    cudaGetSymbolAddress((void**)&p2, g_p2);
    cudaGetSymbolAddress((void**)&c3, g_c3);
    cudaGetSymbolAddress((void**)&p3, g_p3);
    cudaGetSymbolAddress((void**)&c4, g_c4);
    cudaGetSymbolAddress((void**)&p4, g_p4);
    cudaGetSymbolAddress((void**)&br, g_br);
    cudaGetSymbolAddress((void**)&u4, g_u4);
    cudaGetSymbolAddress((void**)&r4, g_r4);
    cudaGetSymbolAddress((void**)&u3, g_u3);
    cudaGetSymbolAddress((void**)&r3, g_r3);
    cudaGetSymbolAddress((void**)&u2, g_u2);
    cudaGetSymbolAddress((void**)&r2, g_r2);
    cudaGetSymbolAddress((void**)&u1, g_u1);
    cudaGetSymbolAddress((void**)&r1, g_r1);
    cudaGetSymbolAddress((void**)&m0, g_m0);
    cudaGetSymbolAddress((void**)&m1, g_m1);
    cudaGetSymbolAddress((void**)&m2, g_m2);
    cudaGetSymbolAddress((void**)&m3, g_m3);
    cudaGetSymbolAddress((void**)&m4, g_m4);
    cudaGetSymbolAddress((void**)&mc4, g_mc4);
    cudaGetSymbolAddress((void**)&mc3, g_mc3);
    cudaGetSymbolAddress((void**)&mc2, g_mc2);
    cudaGetSymbolAddress((void**)&mc1, g_mc1);

    cudaFuncSetAttribute(conv3_smem, cudaFuncAttributeMaxDynamicSharedMemorySize,
                         (int)conv_smem_bytes(1024) + 256);

    const int TB = 256;
    long long n;

    n = (long long)NB * 1024 * 1024 / 4;
    k_init4<<<grid_for(n), TB>>>(x, mask, xm, m0, (int)n);

    // --- encoder ---
    conv3_c1<<<dim3(1024 * 1024 / PX, 1, NB), TB>>>(xm, w_ds1, m0, c1);

    n = (long long)NB * 16 * 512 * 512 / 4;
    k_pool4<<<grid_for(n), TB>>>(c1, m0, p1, m1, NB, 16, 512, 512);

    conv3_smem<<<dim3(256, 2, NB), TB, conv_smem_bytes(512)>>>(
        p1, nullptr, 16, 0, w_ds2, m1, c2, 512, 512, 32);

    n = (long long)NB * 32 * 256 * 256 / 4;
    k_pool4<<<grid_for(n), TB>>>(c2, m1, p2, m2, NB, 32, 256, 256);

    conv3_smem<<<dim3(64, 4, NB), TB, conv_smem_bytes(256)>>>(
        p2, nullptr, 32, 0, w_ds3, m2, c3, 256, 256, 64);

    n = (long long)NB * 64 * 128 * 128 / 4;
    k_pool4<<<grid_for(n), TB>>>(c3, m2, p3, m3, NB, 64, 128, 128);

    conv3_smem<<<dim3(16, 8, NB), TB, conv_smem_bytes(128)>>>(
        p3, nullptr, 64, 0, w_ds4, m3, c4, 128, 128, 128);

    n = (long long)NB * 128 * 64 * 64 / 4;
    k_pool4<<<grid_for(n), TB>>>(c4, m3, p4, m4, NB, 128, 64, 64);

    // --- bridge ---
    conv3_smem<<<dim3(4, 16, NB), TB, conv_smem_bytes(64)>>>(
        p4, nullptr, 128, 0, w_brdg, m4, br, 64, 64, 256);

    // --- decoder 4 ---
    tconv_chw<<<dim3(8, 16, NB), TB>>>(br, wt4, u4, 64, 64, 256, 128);
    n = (long long)NB * 128 * 128 / 4;
    k_mc4<<<grid_for(n), TB>>>(m4, m3, mc4, NB, 128, 128);
    conv3_smem<<<dim3(16, 8, NB), TB, conv_smem_bytes(128)>>>(
        u4, c4, 128, 128, w_us4, mc4, r4, 128, 128, 128);

    // --- decoder 3 ---
    tconv_chw<<<dim3(32, 8, NB), TB>>>(r4, wt3, u3, 128, 128, 128, 64);
    n = (long long)NB * 256 * 256 / 4;
    k_mc4<<<grid_for(n), TB>>>(mc4, m2, mc3, NB, 256, 256);
    conv3_smem<<<dim3(64, 4, NB), TB, conv_smem_bytes(256)>>>(
        u3, c3, 64, 64, w_us3, mc3, r3, 256, 256, 64);

    // --- decoder 2 ---
    tconv_chw<<<dim3(128, 4, NB), TB>>>(r3, wt2, u2, 256, 256, 64, 32);
    n = (long long)NB * 512 * 512 / 4;
    k_mc4<<<grid_for(n), TB>>>(mc3, m1, mc2, NB, 512, 512);
    conv3_smem<<<dim3(256, 2, NB), TB, conv_smem_bytes(512)>>>(
        u2, c2, 32, 32, w_us2, mc2, r2, 512, 512, 32);

    // --- decoder 1 ---
    tconv_chw<<<dim3(512, 2, NB), TB>>>(r2, wt1, u1, 512, 512, 32, 16);
    n = (long long)NB * 1024 * 1024 / 4;
    k_mc4<<<grid_for(n), TB>>>(mc2, m0, mc1, NB, 1024, 1024);
    conv3_smem<<<dim3(1024, 1, NB), TB, conv_smem_bytes(1024)>>>(
        u1, c1, 16, 16, w_us1, mc1, r1, 1024, 1024, 16);

    // --- outputs ---
    n = (long long)NB * 1024 * 1024;
    k_out1x1_chw<<<grid_for(n), TB>>>(r1, w_out, mc1, out_final, 1024 * 1024);

    k_tr_c2<<<dim3(512 * 512 / 32, NB), dim3(32, 8)>>>(c2, c2_out, 512 * 512);
}

// round 16
// speedup vs baseline: 1.1772x; 1.0152x over previous
#include <cuda_runtime.h>

// ---------------------------------------------------------------------------
// SparseUNet, CHW layout. Convs: smem stencil-GEMM with row-padded slabs
// (zero side-pads replace per-tap boundary masks), double-buffered cp.async
// staging of inputs+weights, launch_bounds(256,2). FFMA2 packed math.
// ---------------------------------------------------------------------------

#define NB 2
#define PX 1024      // pixels per conv block
#define CO 16        // output channels per conv block
#define CG 4         // input channels staged per chunk
#define WCHUNK (CG * 9 * CO)   // 576 floats

typedef unsigned long long u64;

__device__ __forceinline__ u64 pk2(float lo, float hi) {
    u64 r; asm("mov.b64 %0,{%1,%2};" : "=l"(r) : "f"(lo), "f"(hi)); return r;
}
__device__ __forceinline__ void upk2(u64 v, float& lo, float& hi) {
    asm("mov.b64 {%0,%1},%2;" : "=f"(lo), "=f"(hi) : "l"(v));
}
__device__ __forceinline__ void ffma2(u64& d, u64 a, u64 b) {
    asm("fma.rn.f32x2 %0,%1,%2,%0;" : "+l"(d) : "l"(a), "l"(b));
}
__device__ __forceinline__ void cpa16(unsigned dst, const float* src, bool ok) {
    int sz = ok ? 16 : 0;
    asm volatile("cp.async.cg.shared.global [%0], [%1], 16, %2;"
                 :: "r"(dst), "l"(src), "r"(sz));
}
__device__ __forceinline__ void cpa_commit() {
    asm volatile("cp.async.commit_group;");
}
template <int N> __device__ __forceinline__ void cpa_wait() {
    asm volatile("cp.async.wait_group %0;" :: "n"(N));
}

// ---- scratch (device globals; allocations forbidden) ----------------------
__device__ float g_xm[NB * 1024 * 1024];
__device__ float g_c1[NB * 16 * 1024 * 1024];
__device__ float g_p1[NB * 16 * 512 * 512];
__device__ float g_c2[NB * 32 * 512 * 512];
__device__ float g_p2[NB * 32 * 256 * 256];
__device__ float g_c3[NB * 64 * 256 * 256];
__device__ float g_p3[NB * 64 * 128 * 128];
__device__ float g_c4[NB * 128 * 128 * 128];
__device__ float g_p4[NB * 128 * 64 * 64];
__device__ float g_br[NB * 256 * 64 * 64];
__device__ float g_u4[NB * 128 * 128 * 128];
__device__ float g_r4[NB * 128 * 128 * 128];
__device__ float g_u3[NB * 64 * 256 * 256];
__device__ float g_r3[NB * 64 * 256 * 256];
__device__ float g_u2[NB * 32 * 512 * 512];
__device__ float g_r2[NB * 32 * 512 * 512];
__device__ float g_u1[NB * 16 * 1024 * 1024];
__device__ float g_r1[NB * 16 * 1024 * 1024];

__device__ unsigned char g_m0[NB * 1024 * 1024];
__device__ unsigned char g_m1[NB * 512 * 512];
__device__ unsigned char g_m2[NB * 256 * 256];
__device__ unsigned char g_m3[NB * 128 * 128];
__device__ unsigned char g_m4[NB * 64 * 64];
__device__ unsigned char g_mc4[NB * 128 * 128];
__device__ unsigned char g_mc3[NB * 256 * 256];
__device__ unsigned char g_mc2[NB * 512 * 512];
__device__ unsigned char g_mc1[NB * 1024 * 1024];

// ---------------------------------------------------------------------------
__global__ void k_init4(const float* __restrict__ x, const int* __restrict__ m,
                        float* __restrict__ xm, unsigned char* __restrict__ m0, int n4) {
    int i = blockIdx.x * blockDim.x + threadIdx.x;
    if (i >= n4) return;
    float4 xv = *reinterpret_cast<const float4*>(x + 4 * (long long)i);
    int4 mv = *reinterpret_cast<const int4*>(m + 4 * (long long)i);
    uchar4 mo;
    mo.x = mv.x != 0; mo.y = mv.y != 0; mo.z = mv.z != 0; mo.w = mv.w != 0;
    float4 o;
    o.x = mo.x ? xv.x : 0.0f;
    o.y = mo.y ? xv.y : 0.0f;
    o.z = mo.z ? xv.z : 0.0f;
    o.w = mo.w ? xv.w : 0.0f;
    *reinterpret_cast<float4*>(xm + 4 * (long long)i) = o;
    *reinterpret_cast<uchar4*>(m0 + 4 * (long long)i) = mo;
}

// ---------------------------------------------------------------------------
// smem-staged 3x3 conv. Input slab stored as rows of (W+8) with 4-col zero
// pads each side -> no boundary masks in the inner loop. OOB rows zero-filled
// by cp.async src-size-0. Double-buffered weights+inputs via cp.async.
// Grid: (px_blocks, co_groups, NB). Block: PX pixels x CO outputs, 256 thr.
// Dynamic smem: [2*WCHUNK][2*CG*SLAB2], SLAB2 = (PX/W + 2) * (W + 8).
// ---------------------------------------------------------------------------
__global__ __launch_bounds__(256, 2)
void conv3_smem(const float* __restrict__ A, const float* __restrict__ Bp,
                int Ca, int Cb,
                const float* __restrict__ w,
                const unsigned char* __restrict__ msk,
                float* __restrict__ out,
                int H, int W, int Cot) {
    extern __shared__ float sm[];
    const int HW = H * W;
    const int Ci = Ca + Cb;
    const int R = PX / W + 2;              // slab rows (incl. y-halo)
    const int RW = W + 8;                  // padded row width
    const int SLAB2 = R * RW;
    float* w_s = sm;                       // 2*WCHUNK
    float* i_s = sm + 2 * WCHUNK;          // 2*CG*SLAB2

    const int b = blockIdx.z;
    const int cobase = blockIdx.y * CO;
    const int tid = threadIdx.x;
    const int p0 = blockIdx.x * PX;
    const int y0 = p0 / W - 1;             // global y of slab row 0 (p0 % W == 0)

    // ---- zero the side pads once (both buffers, all cg slabs, all rows) ----
    for (int e = tid; e < 2 * CG * R * 2; e += 256) {
        int side = e & 1;
        int r = (e >> 1) % R;
        int s2 = (e >> 1) / R;             // buf*CG + cg
        float* row = i_s + s2 * SLAB2 + r * RW;
        float4* pad = reinterpret_cast<float4*>(row + (side ? (W + 4) : 0));
        *pad = make_float4(0.f, 0.f, 0.f, 0.f);
    }

    // ---- per-pixel slab base addresses ----
    int pp[4], basep[4];
#pragma unroll
    for (int p = 0; p < 4; p++) {
        pp[p] = p * 256 + tid;
        int rp = pp[p] / W, xp = pp[p] % W;
        basep[p] = (rp + 1) * RW + 4 + xp; // center tap position in slab
    }

    u64 acc[4][CO / 2];
#pragma unroll
    for (int p = 0; p < 4; p++)
#pragma unroll
        for (int j = 0; j < CO / 2; j++) acc[p][j] = 0ull;

    const int nchunks = W >> 2;            // 16B chunks per data row
    const int nk = Ci / CG;

    auto stage = [&](int k, int buf) {
        const int c0 = k * CG;
        for (int e = tid; e < CG * 9 * 4; e += 256) {
            int f4 = e & 3;
            int tap = (e >> 2) % 9;
            int cg = e / 36;
            const float* src = w + ((long long)tap * Ci + c0 + cg) * Cot + cobase + 4 * f4;
            unsigned d = (unsigned)__cvta_generic_to_shared(
                w_s + buf * WCHUNK + cg * (9 * CO) + tap * CO + 4 * f4);
            cpa16(d, src, true);
        }
        float* dstb = i_s + buf * (CG * SLAB2);
        for (int e = tid; e < CG * R * nchunks; e += 256) {
            int j = e % nchunks;
            int r = (e / nchunks) % R;
            int cg = e / (nchunks * R);
            int ci = c0 + cg;
            const float* plane = (ci < Ca)
                ? A + (long long)(b * Ca + ci) * HW
                : Bp + (long long)(b * Cb + (ci - Ca)) * HW;
            int yg = y0 + r;
            bool ok = (unsigned)yg < (unsigned)H;
            const float* src = plane + (ok ? ((long long)yg * W + (j << 2)) : 0);
            unsigned d = (unsigned)__cvta_generic_to_shared(
                dstb + cg * SLAB2 + r * RW + 4 + (j << 2));
            cpa16(d, src, ok);
        }
    };

    stage(0, 0);
    cpa_commit();

    for (int k = 0; k < nk; k++) {
        if (k + 1 < nk) { stage(k + 1, (k + 1) & 1); cpa_commit(); cpa_wait<1>(); }
        else            { cpa_wait<0>(); }
        __syncthreads();                   // staged data (and pads) visible

        const float* ibuf = i_s + (k & 1) * (CG * SLAB2);
        const float* wbuf = w_s + (k & 1) * WCHUNK;
#pragma unroll
        for (int cg = 0; cg < CG; cg++) {
            const float* s = ibuf + cg * SLAB2;
            const float* wb = wbuf + cg * (9 * CO);
#pragma unroll
            for (int ky = 0; ky < 3; ky++) {
#pragma unroll
                for (int kx = 0; kx < 3; kx++) {
                    const int t = ky * 3 + kx;
                    const ulonglong2* wp =
                        reinterpret_cast<const ulonglong2*>(wb + t * CO);
                    ulonglong2 wa = wp[0];
                    ulonglong2 wc = wp[1];
                    ulonglong2 wd = wp[2];
                    ulonglong2 we = wp[3];
                    const int doff = (ky - 1) * RW + (kx - 1);
#pragma unroll
                    for (int p = 0; p < 4; p++) {
                        float v = s[basep[p] + doff];
                        u64 vv = pk2(v, v);
                        ffma2(acc[p][0], vv, wa.x);
                        ffma2(acc[p][1], vv, wa.y);
                        ffma2(acc[p][2], vv, wc.x);
                        ffma2(acc[p][3], vv, wc.y);
                        ffma2(acc[p][4], vv, wd.x);
                        ffma2(acc[p][5], vv, wd.y);
                        ffma2(acc[p][6], vv, we.x);
                        ffma2(acc[p][7], vv, we.y);
                    }
                }
            }
        }
        __syncthreads();
    }

#pragma unroll
    for (int p = 0; p < 4; p++) {
        int gp = p0 + pp[p];
        bool on = msk[b * HW + gp] != 0;
#pragma unroll
        for (int j = 0; j < CO / 2; j++) {
            float lo, hi;
            upk2(acc[p][j], lo, hi);
            long long o0 = (long long)(b * Cot + cobase + 2 * j) * HW + gp;
            out[o0] = on ? lo : 0.0f;
            out[o0 + HW] = on ? hi : 0.0f;
        }
    }
}

// ---------------------------------------------------------------------------
// ds1 conv: Ci=1, Co=16, W=H=1024. Row-padded slab, no masks.
// ---------------------------------------------------------------------------
__global__ __launch_bounds__(256)
void conv3_c1(const float* __restrict__ A,
              const float* __restrict__ w,
              const unsigned char* __restrict__ msk,
              float* __restrict__ out) {
    const int W = 1024, H = 1024, HW = W * H;
    const int R = PX / W + 2;              // 3
    const int RW = W + 8;
    __shared__ float s_in[3 * (1024 + 8)];
    __shared__ float s_w[9 * CO];

    const int b = blockIdx.z;
    const int tid = threadIdx.x;
    const int p0 = blockIdx.x * PX;
    const int y0 = p0 / W - 1;

    if (tid < 9 * CO) {
        int co = tid & 15, tap = tid >> 4;
        s_w[tid] = w[tap * CO + co];
    }
    // zero pads
    for (int e = tid; e < R * 2; e += 256) {
        int side = e & 1;
        int r = e >> 1;
        float4* pad = reinterpret_cast<float4*>(s_in + r * RW + (side ? (W + 4) : 0));
        *pad = make_float4(0.f, 0.f, 0.f, 0.f);
    }
    for (int e = tid; e < R * (W >> 2); e += 256) {
        int j = e % (W >> 2);
        int r = e / (W >> 2);
        int yg = y0 + r;
        float4 v = make_float4(0.f, 0.f, 0.f, 0.f);
        if ((unsigned)yg < (unsigned)H)
            v = *reinterpret_cast<const float4*>(A + (long long)b * HW + (long long)yg * W + (j << 2));
        *reinterpret_cast<float4*>(s_in + r * RW + 4 + (j << 2)) = v;
    }
    __syncthreads();

    int pp[4], basep[4];
#pragma unroll
    for (int p = 0; p < 4; p++) {
        pp[p] = p * 256 + tid;
        int rp = pp[p] / W, xp = pp[p] % W;
        basep[p] = (rp + 1) * RW + 4 + xp;
    }

    u64 acc[4][CO / 2];
#pragma unroll
    for (int p = 0; p < 4; p++)
#pragma unroll
        for (int j = 0; j < CO / 2; j++) acc[p][j] = 0ull;

#pragma unroll
    for (int ky = 0; ky < 3; ky++) {
#pragma unroll
        for (int kx = 0; kx < 3; kx++) {
            const int t = ky * 3 + kx;
            const ulonglong2* wp = reinterpret_cast<const ulonglong2*>(s_w + t * CO);
            ulonglong2 wa = wp[0], wc = wp[1], wd = wp[2], we = wp[3];
            const int doff = (ky - 1) * RW + (kx - 1);
#pragma unroll
            for (int p = 0; p < 4; p++) {
                float v = s_in[basep[p] + doff];
                u64 vv = pk2(v, v);
                ffma2(acc[p][0], vv, wa.x);
                ffma2(acc[p][1], vv, wa.y);
                ffma2(acc[p][2], vv, wc.x);
                ffma2(acc[p][3], vv, wc.y);
                ffma2(acc[p][4], vv, wd.x);
                ffma2(acc[p][5], vv, wd.y);
                ffma2(acc[p][6], vv, we.x);
                ffma2(acc[p][7], vv, we.y);
            }
        }
    }

#pragma unroll
    for (int p = 0; p < 4; p++) {
        int gp = p0 + pp[p];
        bool on = msk[b * HW + gp] != 0;
#pragma unroll
        for (int j = 0; j < CO / 2; j++) {
            float lo, hi;
            upk2(acc[p][j], lo, hi);
            long long o0 = (long long)(b * CO + 2 * j) * HW + gp;
            out[o0] = on ? lo : 0.0f;
            out[o0 + HW] = on ? hi : 0.0f;
        }
    }
}

// ---------------------------------------------------------------------------
// 2x2 stride-2 masked max pool, 4 outputs/thread; fused mask pool (c==0).
// ---------------------------------------------------------------------------
__global__ void k_pool4(const float* __restrict__ in, const unsigned char* __restrict__ mi,
                        float* __restrict__ out, unsigned char* __restrict__ mo,
                        int B, int C, int Ho, int Wo) {
    const int Wo4 = Wo >> 2;
    long long n = (long long)B * C * Ho * Wo4;
    long long i = (long long)blockIdx.x * blockDim.x + threadIdx.x;
    if (i >= n) return;
    int x4 = (int)(i % Wo4); long long t = i / Wo4;
    int yo = (int)(t % Ho); t /= Ho;
    int c = (int)(t % C);
    int b = (int)(t / C);
    int Wi = Wo * 2, Hi = Ho * 2;

    long long mrow = (long long)(b * Hi + 2 * yo) * Wi + 8 * x4;
    u64 ma = *reinterpret_cast<const u64*>(mi + mrow);
    u64 mb = *reinterpret_cast<const u64*>(mi + mrow + Wi);
    const float* ip = in + ((long long)((b * C + c) * Hi + 2 * yo) * Wi + 8 * x4);
    float4 a0 = *reinterpret_cast<const float4*>(ip);
    float4 a1 = *reinterpret_cast<const float4*>(ip + 4);
    float4 b0 = *reinterpret_cast<const float4*>(ip + Wi);
    float4 b1 = *reinterpret_cast<const float4*>(ip + Wi + 4);
    float va[8] = {a0.x, a0.y, a0.z, a0.w, a1.x, a1.y, a1.z, a1.w};
    float vb[8] = {b0.x, b0.y, b0.z, b0.w, b1.x, b1.y, b1.z, b1.w};

    float o[4];
    unsigned char mq[4];
#pragma unroll
    for (int j = 0; j < 4; j++) {
        int k0 = 2 * j, k1 = 2 * j + 1;
        float best = -3.4e38f; int any = 0;
        if ((ma >> (8 * k0)) & 0xff) { best = fmaxf(best, va[k0]); any = 1; }
        if ((ma >> (8 * k1)) & 0xff) { best = fmaxf(best, va[k1]); any = 1; }
        if ((mb >> (8 * k0)) & 0xff) { best = fmaxf(best, vb[k0]); any = 1; }
        if ((mb >> (8 * k1)) & 0xff) { best = fmaxf(best, vb[k1]); any = 1; }
        o[j] = any ? best : 0.0f;
        mq[j] = (unsigned char)any;
    }
    *reinterpret_cast<float4*>(out + (long long)((b * C + c) * Ho + yo) * Wo + 4 * x4) =
        make_float4(o[0], o[1], o[2], o[3]);
    if (c == 0)
        *reinterpret_cast<uchar4*>(mo + (long long)(b * Ho + yo) * Wo + 4 * x4) =
            make_uchar4(mq[0], mq[1], mq[2], mq[3]);
}

// mc: 4 px per thread
__global__ void k_mc4(const unsigned char* __restrict__ mcoarse,
                      const unsigned char* __restrict__ mfine,
                      unsigned char* __restrict__ mc, int B, int H, int W) {
    int n4 = B * H * W / 4;
    int i = blockIdx.x * blockDim.x + threadIdx.x;
    if (i >= n4) return;
    int px = 4 * i;
    int x = px % W; int t = px / W;
    int y = t % H; int b = t / H;
    uchar4 mf = *reinterpret_cast<const uchar4*>(mfine + px);
    const unsigned char* mcrow = mcoarse + (b * (H / 2) + (y >> 1)) * (W / 2) + (x >> 1);
    unsigned char c0 = mcrow[0], c1 = mcrow[1];
    uchar4 o;
    o.x = (mf.x | c0) ? 1 : 0;
    o.y = (mf.y | c0) ? 1 : 0;
    o.z = (mf.z | c1) ? 1 : 0;
    o.w = (mf.w | c1) ? 1 : 0;
    *reinterpret_cast<uchar4*>(mc + px) = o;
}

// ---------------------------------------------------------------------------
// kernel-2 stride-2 tconv, CHW; 2 input px x 8 co per thread; weights in smem.
// ---------------------------------------------------------------------------
__global__ __launch_bounds__(256)
void tconv_chw(const float* __restrict__ in, const float* __restrict__ w,
               float* __restrict__ out, int Hi, int Wi, int Ci, int Co) {
    __shared__ float s_w[256 * 32];        // max Ci=256: 32KB
    const int HWi = Hi * Wi;
    const int HWo = HWi * 4;
    const int Wo = Wi * 2;
    const int b = blockIdx.z;
    const int cobase = blockIdx.y * 8;
    const int tid = threadIdx.x;

    for (int e = tid; e < Ci * 32; e += 256) {
        int j = e & 7;
        int dt = (e >> 3) & 3;
        int ci = e >> 5;
        s_w[ci * 32 + dt * 8 + j] = w[((long long)dt * Ci + ci) * Co + cobase + j];
    }
    __syncthreads();

    int p0 = blockIdx.x * 512 + tid;
    int p1 = p0 + 256;
    bool v0 = p0 < HWi, v1 = p1 < HWi;

    u64 acc[2][4][4];
#pragma unroll
    for (int q = 0; q < 2; q++)
#pragma unroll
        for (int dt = 0; dt < 4; dt++)
#pragma unroll
            for (int j = 0; j < 4; j++) acc[q][dt][j] = 0ull;

    for (int ci = 0; ci < Ci; ci++) {
        const ulonglong2* wr = reinterpret_cast<const ulonglong2*>(s_w + ci * 32);
        const float* ip = in + (long long)(b * Ci + ci) * HWi;
        float x0 = v0 ? __ldg(ip + p0) : 0.0f;
        float x1 = v1 ? __ldg(ip + p1) : 0.0f;
        u64 xx0 = pk2(x0, x0), xx1 = pk2(x1, x1);
#pragma unroll
        for (int dt = 0; dt < 4; dt++) {
            ulonglong2 wlo = wr[2 * dt];
            ulonglong2 whi = wr[2 * dt + 1];
            ffma2(acc[0][dt][0], xx0, wlo.x); ffma2(acc[0][dt][1], xx0, wlo.y);
            ffma2(acc[0][dt][2], xx0, whi.x); ffma2(acc[0][dt][3], xx0, whi.y);
            ffma2(acc[1][dt][0], xx1, wlo.x); ffma2(acc[1][dt][1], xx1, wlo.y);
            ffma2(acc[1][dt][2], xx1, whi.x); ffma2(acc[1][dt][3], xx1, whi.y);
        }
    }

    int ps[2] = {p0, p1};
    bool vs[2] = {v0, v1};
#pragma unroll
    for (int q = 0; q < 2; q++) {
        if (!vs[q]) continue;
        int y = ps[q] / Wi, x = ps[q] % Wi;
        long long obase = (long long)(b * Co + cobase) * HWo;
#pragma unroll
        for (int dt = 0; dt < 4; dt++) {
            int yo = 2 * y + (dt >> 1);
            int xo = 2 * x + (dt & 1);
            long long oo = obase + (long long)yo * Wo + xo;
#pragma unroll
            for (int j = 0; j < 4; j++) {
                float lo, hi;
                upk2(acc[q][dt][j], lo, hi);
                out[oo + (long long)(2 * j) * HWo] = lo;
                out[oo + (long long)(2 * j + 1) * HWo] = hi;
            }
        }
    }
}

// final 1x1 conv 16->3, CHW in, NHWC out
__global__ void k_out1x1_chw(const float* __restrict__ in, const float* __restrict__ w,
                             const unsigned char* __restrict__ msk,
                             float* __restrict__ out, int HW) {
    int n = NB * HW;
    int i = blockIdx.x * blockDim.x + threadIdx.x;
    if (i >= n) return;
    long long o = (long long)i * 3;
    if (!msk[i]) { out[o] = 0.0f; out[o + 1] = 0.0f; out[o + 2] = 0.0f; return; }
    int b = i / HW, pix = i % HW;
    float a0 = 0.0f, a1 = 0.0f, a2 = 0.0f;
#pragma unroll
    for (int c = 0; c < 16; c++) {
        float v = __ldg(in + (long long)(b * 16 + c) * HW + pix);
        a0 = fmaf(v, w[c * 3 + 0], a0);
        a1 = fmaf(v, w[c * 3 + 1], a1);
        a2 = fmaf(v, w[c * 3 + 2], a2);
    }
    out[o] = a0; out[o + 1] = a1; out[o + 2] = a2;
}

// CHW [B,32,HW] -> NHWC [B,HW,32]
__global__ void k_tr_c2(const float* __restrict__ in, float* __restrict__ outp, int HW) {
    __shared__ float t[32][33];
    int b = blockIdx.y;
    int px0 = blockIdx.x * 32;
    int tx = threadIdx.x, ty = threadIdx.y;
#pragma unroll
    for (int k = 0; k < 4; k++) {
        int c = ty + k * 8;
        t[c][tx] = in[(long long)(b * 32 + c) * HW + px0 + tx];
    }
    __syncthreads();
#pragma unroll
    for (int k = 0; k < 4; k++) {
        int pl = ty + k * 8;
        outp[((long long)b * HW + px0 + pl) * 32 + tx] = t[tx][pl];
    }
}

// ---------------------------------------------------------------------------
static inline unsigned grid_for(long long n) { return (unsigned)((n + 255) / 256); }

static inline size_t conv_smem_bytes(int W) {
    int R = PX / W + 2;
    return (size_t)(2 * WCHUNK + 2 * CG * R * (W + 8)) * sizeof(float);
}

extern "C" void kernel_launch(void* const* d_in, const int* in_sizes, int n_in,
                              void* d_out, int out_size) {
    (void)in_sizes; (void)n_in; (void)out_size;

    const float* x      = (const float*)d_in[0];
    const int*   mask   = (const int*)d_in[1];
    const float* w_ds1  = (const float*)d_in[2];
    const float* w_ds2  = (const float*)d_in[3];
    const float* w_ds3  = (const float*)d_in[4];
    const float* w_ds4  = (const float*)d_in[5];
    const float* w_brdg = (const float*)d_in[6];
    const float* wt4    = (const float*)d_in[7];
    const float* w_us4  = (const float*)d_in[8];
    const float* wt3    = (const float*)d_in[9];
    const float* w_us3  = (const float*)d_in[10];
    const float* wt2    = (const float*)d_in[11];
    const float* w_us2  = (const float*)d_in[12];
    const float* wt1    = (const float*)d_in[13];
    const float* w_us1  = (const float*)d_in[14];
    const float* w_out  = (const float*)d_in[15];

    float* out_final = (float*)d_out;                                    // [2,1024,1024,3]
    float* c2_out    = (float*)d_out + (long long)NB * 1024 * 1024 * 3;  // [2,512,512,32]

    float *xm, *c1, *p1, *c2, *p2, *c3, *p3, *c4, *p4, *br, *u4, *r4, *u3, *r3, *u2, *r2, *u1, *r1;
    unsigned char *m0, *m1, *m2, *m3, *m4, *mc4, *mc3, *mc2, *mc1;
    cudaGetSymbolAddress((void**)&xm, g_xm);
    cudaGetSymbolAddress((void**)&c1, g_c1);
    cudaGetSymbolAddress((void**)&p1, g_p1);
    cudaGetSymbolAddress((void**)&c2, g_c2);
    cudaGetSymbolAddress((void**)&p2, g_p2);
    cudaGetSymbolAddress((void**)&c3, g_c3);
    cudaGetSymbolAddress((void**)&p3, g_p3);
    cudaGetSymbolAddress((void**)&c4, g_c4);
    cudaGetSymbolAddress((void**)&p4, g_p4);
    cudaGetSymbolAddress((void**)&br, g_br);
    cudaGetSymbolAddress((void**)&u4, g_u4);
    cudaGetSymbolAddress((void**)&r4, g_r4);
    cudaGetSymbolAddress((void**)&u3, g_u3);
    cudaGetSymbolAddress((void**)&r3, g_r3);
    cudaGetSymbolAddress((void**)&u2, g_u2);
    cudaGetSymbolAddress((void**)&r2, g_r2);
    cudaGetSymbolAddress((void**)&u1, g_u1);
    cudaGetSymbolAddress((void**)&r1, g_r1);
    cudaGetSymbolAddress((void**)&m0, g_m0);
    cudaGetSymbolAddress((void**)&m1, g_m1);
    cudaGetSymbolAddress((void**)&m2, g_m2);
    cudaGetSymbolAddress((void**)&m3, g_m3);
    cudaGetSymbolAddress((void**)&m4, g_m4);
    cudaGetSymbolAddress((void**)&mc4, g_mc4);
    cudaGetSymbolAddress((void**)&mc3, g_mc3);
    cudaGetSymbolAddress((void**)&mc2, g_mc2);
    cudaGetSymbolAddress((void**)&mc1, g_mc1);

    cudaFuncSetAttribute(conv3_smem, cudaFuncAttributeMaxDynamicSharedMemorySize,
                         (int)conv_smem_bytes(1024) + 256);

    const int TB = 256;
    long long n;

    n = (long long)NB * 1024 * 1024 / 4;
    k_init4<<<grid_for(n), TB>>>(x, mask, xm, m0, (int)n);

    // --- encoder ---
    conv3_c1<<<dim3(1024 * 1024 / PX, 1, NB), TB>>>(xm, w_ds1, m0, c1);

    n = (long long)NB * 16 * 512 * 512 / 4;
    k_pool4<<<grid_for(n), TB>>>(c1, m0, p1, m1, NB, 16, 512, 512);

    conv3_smem<<<dim3(256, 2, NB), TB, conv_smem_bytes(512)>>>(
        p1, nullptr, 16, 0, w_ds2, m1, c2, 512, 512, 32);

    n = (long long)NB * 32 * 256 * 256 / 4;
    k_pool4<<<grid_for(n), TB>>>(c2, m1, p2, m2, NB, 32, 256, 256);

    conv3_smem<<<dim3(64, 4, NB), TB, conv_smem_bytes(256)>>>(
        p2, nullptr, 32, 0, w_ds3, m2, c3, 256, 256, 64);

    n = (long long)NB * 64 * 128 * 128 / 4;
    k_pool4<<<grid_for(n), TB>>>(c3, m2, p3, m3, NB, 64, 128, 128);

    conv3_smem<<<dim3(16, 8, NB), TB, conv_smem_bytes(128)>>>(
        p3, nullptr, 64, 0, w_ds4, m3, c4, 128, 128, 128);

    n = (long long)NB * 128 * 64 * 64 / 4;
    k_pool4<<<grid_for(n), TB>>>(c4, m3, p4, m4, NB, 128, 64, 64);

    // --- bridge ---
    conv3_smem<<<dim3(4, 16, NB), TB, conv_smem_bytes(64)>>>(
        p4, nullptr, 128, 0, w_brdg, m4, br, 64, 64, 256);

    // --- decoder 4 ---
    tconv_chw<<<dim3(8, 16, NB), TB>>>(br, wt4, u4, 64, 64, 256, 128);
    n = (long long)NB * 128 * 128 / 4;
    k_mc4<<<grid_for(n), TB>>>(m4, m3, mc4, NB, 128, 128);
    conv3_smem<<<dim3(16, 8, NB), TB, conv_smem_bytes(128)>>>(
        u4, c4, 128, 128, w_us4, mc4, r4, 128, 128, 128);

    // --- decoder 3 ---
    tconv_chw<<<dim3(32, 8, NB), TB>>>(r4, wt3, u3, 128, 128, 128, 64);
    n = (long long)NB * 256 * 256 / 4;
    k_mc4<<<grid_for(n), TB>>>(mc4, m2, mc3, NB, 256, 256);
    conv3_smem<<<dim3(64, 4, NB), TB, conv_smem_bytes(256)>>>(
        u3, c3, 64, 64, w_us3, mc3, r3, 256, 256, 64);

    // --- decoder 2 ---
    tconv_chw<<<dim3(128, 4, NB), TB>>>(r3, wt2, u2, 256, 256, 64, 32);
    n = (long long)NB * 512 * 512 / 4;
    k_mc4<<<grid_for(n), TB>>>(mc3, m1, mc2, NB, 512, 512);
    conv3_smem<<<dim3(256, 2, NB), TB, conv_smem_bytes(512)>>>(
        u2, c2, 32, 32, w_us2, mc2, r2, 512, 512, 32);

    // --- decoder 1 ---
    tconv_chw<<<dim3(512, 2, NB), TB>>>(r2, wt1, u1, 512, 512, 32, 16);
    n = (long long)NB * 1024 * 1024 / 4;
    k_mc4<<<grid_for(n), TB>>>(mc2, m0, mc1, NB, 1024, 1024);
    conv3_smem<<<dim3(1024, 1, NB), TB, conv_smem_bytes(1024)>>>(
        u1, c1, 16, 16, w_us1, mc1, r1, 1024, 1024, 16);

    // --- outputs ---
    n = (long long)NB * 1024 * 1024;
    k_out1x1_chw<<<grid_for(n), TB>>>(r1, w_out, mc1, out_final, 1024 * 1024);

    k_tr_c2<<<dim3(512 * 512 / 32, NB), dim3(32, 8)>>>(c2, c2_out, 512 * 512);
}

// round 17
// speedup vs baseline: 1.3702x; 1.1639x over previous
#include <cuda_runtime.h>

// ---------------------------------------------------------------------------
// SparseUNet, CHW layout. Convs: smem stencil-GEMM, row-padded slabs,
// double-buffered cp.async staging, CG=4 (W>=512) / CG=8 (W<=256),
// pow2 shift indexing in staging, launch_bounds(256,2). FFMA2 math.
// Init fused into the first conv.
// ---------------------------------------------------------------------------

#define NB 2
#define PX 1024      // pixels per conv block
#define CO 16        // output channels per conv block

typedef unsigned long long u64;

__device__ __forceinline__ u64 pk2(float lo, float hi) {
    u64 r; asm("mov.b64 %0,{%1,%2};" : "=l"(r) : "f"(lo), "f"(hi)); return r;
}
__device__ __forceinline__ void upk2(u64 v, float& lo, float& hi) {
    asm("mov.b64 {%0,%1},%2;" : "=f"(lo), "=f"(hi) : "l"(v));
}
__device__ __forceinline__ void ffma2(u64& d, u64 a, u64 b) {
    asm("fma.rn.f32x2 %0,%1,%2,%0;" : "+l"(d) : "l"(a), "l"(b));
}
__device__ __forceinline__ void cpa16(unsigned dst, const float* src, bool ok) {
    int sz = ok ? 16 : 0;
    asm volatile("cp.async.cg.shared.global [%0], [%1], 16, %2;"
                 :: "r"(dst), "l"(src), "r"(sz));
}
__device__ __forceinline__ void cpa_commit() {
    asm volatile("cp.async.commit_group;");
}
template <int N> __device__ __forceinline__ void cpa_wait() {
    asm volatile("cp.async.wait_group %0;" :: "n"(N));
}

// ---- scratch (device globals; allocations forbidden) ----------------------
__device__ float g_c1[NB * 16 * 1024 * 1024];
__device__ float g_p1[NB * 16 * 512 * 512];
__device__ float g_c2[NB * 32 * 512 * 512];
__device__ float g_p2[NB * 32 * 256 * 256];
__device__ float g_c3[NB * 64 * 256 * 256];
__device__ float g_p3[NB * 64 * 128 * 128];
__device__ float g_c4[NB * 128 * 128 * 128];
__device__ float g_p4[NB * 128 * 64 * 64];
__device__ float g_br[NB * 256 * 64 * 64];
__device__ float g_u4[NB * 128 * 128 * 128];
__device__ float g_r4[NB * 128 * 128 * 128];
__device__ float g_u3[NB * 64 * 256 * 256];
__device__ float g_r3[NB * 64 * 256 * 256];
__device__ float g_u2[NB * 32 * 512 * 512];
__device__ float g_r2[NB * 32 * 512 * 512];
__device__ float g_u1[NB * 16 * 1024 * 1024];
__device__ float g_r1[NB * 16 * 1024 * 1024];

__device__ unsigned char g_m0[NB * 1024 * 1024];
__device__ unsigned char g_m1[NB * 512 * 512];
__device__ unsigned char g_m2[NB * 256 * 256];
__device__ unsigned char g_m3[NB * 128 * 128];
__device__ unsigned char g_m4[NB * 64 * 64];
__device__ unsigned char g_mc4[NB * 128 * 128];
__device__ unsigned char g_mc3[NB * 256 * 256];
__device__ unsigned char g_mc2[NB * 512 * 512];
__device__ unsigned char g_mc1[NB * 1024 * 1024];

// ---------------------------------------------------------------------------
// smem-staged 3x3 conv, CGT channels per chunk (template), pow2 shift staging.
// Grid: (px_blocks, co_groups, NB). Dynamic smem: [2*WCH][2*CGT*SLAB2].
// ---------------------------------------------------------------------------
template <int CGT, int LCG>
__global__ __launch_bounds__(256, 2)
void conv3_smem(const float* __restrict__ A, const float* __restrict__ Bp,
                int Ca, int Cb,
                const float* __restrict__ w,
                const unsigned char* __restrict__ msk,
                float* __restrict__ out,
                int H, int W, int lw, int Cot) {
    extern __shared__ float sm[];
    const int HW = H * W;
    const int Ci = Ca + Cb;
    const int R = (PX >> lw) + 2;          // slab rows (incl. y-halo)
    const int RW = W + 8;                  // padded row width
    const int SLAB2 = R * RW;
    const int WCH = CGT * 9 * CO;
    float* w_s = sm;                       // 2*WCH
    float* i_s = sm + 2 * WCH;             // 2*CGT*SLAB2

    const int b = blockIdx.z;
    const int cobase = blockIdx.y * CO;
    const int tid = threadIdx.x;
    const int p0 = blockIdx.x * PX;
    const int y0 = (p0 >> lw) - 1;

    // ---- zero the side pads once ----
    for (int e = tid; e < 2 * CGT * R * 2; e += 256) {
        int side = e & 1;
        int r = (e >> 1) % R;
        int s2 = (e >> 1) / R;
        float* row = i_s + s2 * SLAB2 + r * RW;
        float4* pad = reinterpret_cast<float4*>(row + (side ? (W + 4) : 0));
        *pad = make_float4(0.f, 0.f, 0.f, 0.f);
    }

    // ---- per-pixel slab base addresses ----
    int pp[4], basep[4];
#pragma unroll
    for (int p = 0; p < 4; p++) {
        pp[p] = p * 256 + tid;
        int rp = pp[p] >> lw, xp = pp[p] & (W - 1);
        basep[p] = (rp + 1) * RW + 4 + xp;
    }

    u64 acc[4][CO / 2];
#pragma unroll
    for (int p = 0; p < 4; p++)
#pragma unroll
        for (int j = 0; j < CO / 2; j++) acc[p][j] = 0ull;

    const int nch_sh = lw - 2;             // log2(chunks per row)
    const int cgn_sh = nch_sh + LCG;       // log2(CGT * chunks per row)
    const int nstage = CGT * R << nch_sh;
    const int nk = Ci >> LCG;

    auto stage = [&](int k, int buf) {
        const int c0 = k << LCG;
        for (int e = tid; e < CGT * 9 * 4; e += 256) {
            int f4 = e & 3;
            int tap = (e >> 2) % 9;
            int cg = e / 36;
            const float* src = w + ((long long)tap * Ci + c0 + cg) * Cot + cobase + 4 * f4;
            unsigned d = (unsigned)__cvta_generic_to_shared(
                w_s + buf * WCH + cg * (9 * CO) + tap * CO + 4 * f4);
            cpa16(d, src, true);
        }
        float* dstb = i_s + buf * (CGT * SLAB2);
        for (int e = tid; e < nstage; e += 256) {
            int r = e >> cgn_sh;
            int rem = e & ((1 << cgn_sh) - 1);
            int cg = rem >> nch_sh;
            int j = rem & ((1 << nch_sh) - 1);
            int ci = c0 + cg;
            const float* plane = (ci < Ca)
                ? A + (long long)(b * Ca + ci) * HW
                : Bp + (long long)(b * Cb + (ci - Ca)) * HW;
            int yg = y0 + r;
            bool ok = (unsigned)yg < (unsigned)H;
            const float* src = plane + (ok ? (((long long)yg << lw) + (j << 2)) : 0);
            unsigned d = (unsigned)__cvta_generic_to_shared(
                dstb + cg * SLAB2 + r * RW + 4 + (j << 2));
            cpa16(d, src, ok);
        }
    };

    stage(0, 0);
    cpa_commit();

    for (int k = 0; k < nk; k++) {
        if (k + 1 < nk) { stage(k + 1, (k + 1) & 1); cpa_commit(); cpa_wait<1>(); }
        else            { cpa_wait<0>(); }
        __syncthreads();

        const float* ibuf = i_s + (k & 1) * (CGT * SLAB2);
        const float* wbuf = w_s + (k & 1) * WCH;
#pragma unroll
        for (int cg = 0; cg < CGT; cg++) {
            const float* s = ibuf + cg * SLAB2;
            const float* wb = wbuf + cg * (9 * CO);
#pragma unroll
            for (int ky = 0; ky < 3; ky++) {
#pragma unroll
                for (int kx = 0; kx < 3; kx++) {
                    const int t = ky * 3 + kx;
                    const ulonglong2* wp =
                        reinterpret_cast<const ulonglong2*>(wb + t * CO);
                    ulonglong2 wa = wp[0];
                    ulonglong2 wc = wp[1];
                    ulonglong2 wd = wp[2];
                    ulonglong2 we = wp[3];
                    const int doff = (ky - 1) * RW + (kx - 1);
#pragma unroll
                    for (int p = 0; p < 4; p++) {
                        float v = s[basep[p] + doff];
                        u64 vv = pk2(v, v);
                        ffma2(acc[p][0], vv, wa.x);
                        ffma2(acc[p][1], vv, wa.y);
                        ffma2(acc[p][2], vv, wc.x);
                        ffma2(acc[p][3], vv, wc.y);
                        ffma2(acc[p][4], vv, wd.x);
                        ffma2(acc[p][5], vv, wd.y);
                        ffma2(acc[p][6], vv, we.x);
                        ffma2(acc[p][7], vv, we.y);
                    }
                }
            }
        }
        __syncthreads();
    }

#pragma unroll
    for (int p = 0; p < 4; p++) {
        int gp = p0 + pp[p];
        bool on = msk[b * HW + gp] != 0;
#pragma unroll
        for (int j = 0; j < CO / 2; j++) {
            float lo, hi;
            upk2(acc[p][j], lo, hi);
            long long o0 = (long long)(b * Cot + cobase + 2 * j) * HW + gp;
            out[o0] = on ? lo : 0.0f;
            out[o0 + HW] = on ? hi : 0.0f;
        }
    }
}

// ---------------------------------------------------------------------------
// Fused init + ds1 conv: reads raw x + mask, writes m0 and c1.
// Ci=1, Co=16, W=H=1024; each block = one image row (+halo).
// ---------------------------------------------------------------------------
__global__ __launch_bounds__(256)
void conv3_c1(const float* __restrict__ x, const int* __restrict__ mask,
              const float* __restrict__ w,
              unsigned char* __restrict__ m0,
              float* __restrict__ out) {
    const int W = 1024, H = 1024, HW = W * H;
    const int R = 3;
    const int RW = W + 8;
    __shared__ float s_in[3 * (1024 + 8)];
    __shared__ unsigned char s_m[1024];
    __shared__ float s_w[9 * CO];

    const int b = blockIdx.z;
    const int tid = threadIdx.x;
    const int p0 = blockIdx.x * PX;        // = row index * W
    const int y0 = (p0 >> 10) - 1;

    if (tid < 9 * CO) {
        int co = tid & 15, tap = tid >> 4;
        s_w[tid] = w[tap * CO + co];
    }
    for (int e = tid; e < R * 2; e += 256) {
        int side = e & 1;
        int r = e >> 1;
        float4* pad = reinterpret_cast<float4*>(s_in + r * RW + (side ? (W + 4) : 0));
        *pad = make_float4(0.f, 0.f, 0.f, 0.f);
    }
    // stage 3 rows of masked input; center row also writes m0 (global + smem)
    for (int e = tid; e < R * (W >> 2); e += 256) {
        int j = e & ((W >> 2) - 1);
        int r = e >> 8;                    // W>>2 = 256
        int yg = y0 + r;
        float4 v = make_float4(0.f, 0.f, 0.f, 0.f);
        if ((unsigned)yg < (unsigned)H) {
            long long gbase = (long long)b * HW + ((long long)yg << 10) + (j << 2);
            float4 xv = *reinterpret_cast<const float4*>(x + gbase);
            int4 mv = *reinterpret_cast<const int4*>(mask + gbase);
            uchar4 mb;
            mb.x = mv.x != 0; mb.y = mv.y != 0; mb.z = mv.z != 0; mb.w = mv.w != 0;
            v.x = mb.x ? xv.x : 0.0f;
            v.y = mb.y ? xv.y : 0.0f;
            v.z = mb.z ? xv.z : 0.0f;
            v.w = mb.w ? xv.w : 0.0f;
            if (r == 1) {
                *reinterpret_cast<uchar4*>(m0 + gbase) = mb;
                *reinterpret_cast<uchar4*>(s_m + (j << 2)) = mb;
            }
        }
        *reinterpret_cast<float4*>(s_in + r * RW + 4 + (j << 2)) = v;
    }
    __syncthreads();

    int basep[4];
#pragma unroll
    for (int p = 0; p < 4; p++) basep[p] = RW + 4 + p * 256 + tid;

    u64 acc[4][CO / 2];
#pragma unroll
    for (int p = 0; p < 4; p++)
#pragma unroll
        for (int j = 0; j < CO / 2; j++) acc[p][j] = 0ull;

#pragma unroll
    for (int ky = 0; ky < 3; ky++) {
#pragma unroll
        for (int kx = 0; kx < 3; kx++) {
            const int t = ky * 3 + kx;
            const ulonglong2* wp = reinterpret_cast<const ulonglong2*>(s_w + t * CO);
            ulonglong2 wa = wp[0], wc = wp[1], wd = wp[2], we = wp[3];
            const int doff = (ky - 1) * RW + (kx - 1);
#pragma unroll
            for (int p = 0; p < 4; p++) {
                float v = s_in[basep[p] + doff];
                u64 vv = pk2(v, v);
                ffma2(acc[p][0], vv, wa.x);
                ffma2(acc[p][1], vv, wa.y);
                ffma2(acc[p][2], vv, wc.x);
                ffma2(acc[p][3], vv, wc.y);
                ffma2(acc[p][4], vv, wd.x);
                ffma2(acc[p][5], vv, wd.y);
                ffma2(acc[p][6], vv, we.x);
                ffma2(acc[p][7], vv, we.y);
            }
        }
    }

#pragma unroll
    for (int p = 0; p < 4; p++) {
        int xp = p * 256 + tid;
        int gp = p0 + xp;
        bool on = s_m[xp] != 0;
#pragma unroll
        for (int j = 0; j < CO / 2; j++) {
            float lo, hi;
            upk2(acc[p][j], lo, hi);
            long long o0 = (long long)(b * CO + 2 * j) * HW + gp;
            out[o0] = on ? lo : 0.0f;
            out[o0 + HW] = on ? hi : 0.0f;
        }
    }
}

// ---------------------------------------------------------------------------
// 2x2 stride-2 masked max pool, 4 outputs/thread; fused mask pool (c==0).
// ---------------------------------------------------------------------------
__global__ void k_pool4(const float* __restrict__ in, const unsigned char* __restrict__ mi,
                        float* __restrict__ out, unsigned char* __restrict__ mo,
                        int B, int C, int Ho, int Wo) {
    const int Wo4 = Wo >> 2;
    long long n = (long long)B * C * Ho * Wo4;
    long long i = (long long)blockIdx.x * blockDim.x + threadIdx.x;
    if (i >= n) return;
    int x4 = (int)(i % Wo4); long long t = i / Wo4;
    int yo = (int)(t % Ho); t /= Ho;
    int c = (int)(t % C);
    int b = (int)(t / C);
    int Wi = Wo * 2, Hi = Ho * 2;

    long long mrow = (long long)(b * Hi + 2 * yo) * Wi + 8 * x4;
    u64 ma = *reinterpret_cast<const u64*>(mi + mrow);
    u64 mb = *reinterpret_cast<const u64*>(mi + mrow + Wi);
    const float* ip = in + ((long long)((b * C + c) * Hi + 2 * yo) * Wi + 8 * x4);
    float4 a0 = *reinterpret_cast<const float4*>(ip);
    float4 a1 = *reinterpret_cast<const float4*>(ip + 4);
    float4 b0 = *reinterpret_cast<const float4*>(ip + Wi);
    float4 b1 = *reinterpret_cast<const float4*>(ip + Wi + 4);
    float va[8] = {a0.x, a0.y, a0.z, a0.w, a1.x, a1.y, a1.z, a1.w};
    float vb[8] = {b0.x, b0.y, b0.z, b0.w, b1.x, b1.y, b1.z, b1.w};

    float o[4];
    unsigned char mq[4];
#pragma unroll
    for (int j = 0; j < 4; j++) {
        int k0 = 2 * j, k1 = 2 * j + 1;
        float best = -3.4e38f; int any = 0;
        if ((ma >> (8 * k0)) & 0xff) { best = fmaxf(best, va[k0]); any = 1; }
        if ((ma >> (8 * k1)) & 0xff) { best = fmaxf(best, va[k1]); any = 1; }
        if ((mb >> (8 * k0)) & 0xff) { best = fmaxf(best, vb[k0]); any = 1; }
        if ((mb >> (8 * k1)) & 0xff) { best = fmaxf(best, vb[k1]); any = 1; }
        o[j] = any ? best : 0.0f;
        mq[j] = (unsigned char)any;
    }
    *reinterpret_cast<float4*>(out + (long long)((b * C + c) * Ho + yo) * Wo + 4 * x4) =
        make_float4(o[0], o[1], o[2], o[3]);
    if (c == 0)
        *reinterpret_cast<uchar4*>(mo + (long long)(b * Ho + yo) * Wo + 4 * x4) =
            make_uchar4(mq[0], mq[1], mq[2], mq[3]);
}

// mc: 4 px per thread
__global__ void k_mc4(const unsigned char* __restrict__ mcoarse,
                      const unsigned char* __restrict__ mfine,
                      unsigned char* __restrict__ mc, int B, int H, int W) {
    int n4 = B * H * W / 4;
    int i = blockIdx.x * blockDim.x + threadIdx.x;
    if (i >= n4) return;
    int px = 4 * i;
    int x = px % W; int t = px / W;
    int y = t % H; int b = t / H;
    uchar4 mf = *reinterpret_cast<const uchar4*>(mfine + px);
    const unsigned char* mcrow = mcoarse + (b * (H / 2) + (y >> 1)) * (W / 2) + (x >> 1);
    unsigned char c0 = mcrow[0], c1 = mcrow[1];
    uchar4 o;
    o.x = (mf.x | c0) ? 1 : 0;
    o.y = (mf.y | c0) ? 1 : 0;
    o.z = (mf.z | c1) ? 1 : 0;
    o.w = (mf.w | c1) ? 1 : 0;
    *reinterpret_cast<uchar4*>(mc + px) = o;
}

// ---------------------------------------------------------------------------
// kernel-2 stride-2 tconv, CHW; 2 input px x 8 co per thread; weights in smem.
// ---------------------------------------------------------------------------
__global__ __launch_bounds__(256)
void tconv_chw(const float* __restrict__ in, const float* __restrict__ w,
               float* __restrict__ out, int Hi, int Wi, int Ci, int Co) {
    __shared__ float s_w[256 * 32];        // max Ci=256: 32KB
    const int HWi = Hi * Wi;
    const int HWo = HWi * 4;
    const int Wo = Wi * 2;
    const int b = blockIdx.z;
    const int cobase = blockIdx.y * 8;
    const int tid = threadIdx.x;

    for (int e = tid; e < Ci * 32; e += 256) {
        int j = e & 7;
        int dt = (e >> 3) & 3;
        int ci = e >> 5;
        s_w[ci * 32 + dt * 8 + j] = w[((long long)dt * Ci + ci) * Co + cobase + j];
    }
    __syncthreads();

    int p0 = blockIdx.x * 512 + tid;
    int p1 = p0 + 256;
    bool v0 = p0 < HWi, v1 = p1 < HWi;

    u64 acc[2][4][4];
#pragma unroll
    for (int q = 0; q < 2; q++)
#pragma unroll
        for (int dt = 0; dt < 4; dt++)
#pragma unroll
            for (int j = 0; j < 4; j++) acc[q][dt][j] = 0ull;

    for (int ci = 0; ci < Ci; ci++) {
        const ulonglong2* wr = reinterpret_cast<const ulonglong2*>(s_w + ci * 32);
        const float* ip = in + (long long)(b * Ci + ci) * HWi;
        float x0 = v0 ? __ldg(ip + p0) : 0.0f;
        float x1 = v1 ? __ldg(ip + p1) : 0.0f;
        u64 xx0 = pk2(x0, x0), xx1 = pk2(x1, x1);
#pragma unroll
        for (int dt = 0; dt < 4; dt++) {
            ulonglong2 wlo = wr[2 * dt];
            ulonglong2 whi = wr[2 * dt + 1];
            ffma2(acc[0][dt][0], xx0, wlo.x); ffma2(acc[0][dt][1], xx0, wlo.y);
            ffma2(acc[0][dt][2], xx0, whi.x); ffma2(acc[0][dt][3], xx0, whi.y);
            ffma2(acc[1][dt][0], xx1, wlo.x); ffma2(acc[1][dt][1], xx1, wlo.y);
            ffma2(acc[1][dt][2], xx1, whi.x); ffma2(acc[1][dt][3], xx1, whi.y);
        }
    }

    int ps[2] = {p0, p1};
    bool vs[2] = {v0, v1};
#pragma unroll
    for (int q = 0; q < 2; q++) {
        if (!vs[q]) continue;
        int y = ps[q] / Wi, x = ps[q] % Wi;
        long long obase = (long long)(b * Co + cobase) * HWo;
#pragma unroll
        for (int dt = 0; dt < 4; dt++) {
            int yo = 2 * y + (dt >> 1);
            int xo = 2 * x + (dt & 1);
            long long oo = obase + (long long)yo * Wo + xo;
#pragma unroll
            for (int j = 0; j < 4; j++) {
                float lo, hi;
                upk2(acc[q][dt][j], lo, hi);
                out[oo + (long long)(2 * j) * HWo] = lo;
                out[oo + (long long)(2 * j + 1) * HWo] = hi;
            }
        }
    }
}

// final 1x1 conv 16->3, CHW in, NHWC out
__global__ void k_out1x1_chw(const float* __restrict__ in, const float* __restrict__ w,
                             const unsigned char* __restrict__ msk,
                             float* __restrict__ out, int HW) {
    int n = NB * HW;
    int i = blockIdx.x * blockDim.x + threadIdx.x;
    if (i >= n) return;
    long long o = (long long)i * 3;
    if (!msk[i]) { out[o] = 0.0f; out[o + 1] = 0.0f; out[o + 2] = 0.0f; return; }
    int b = i / HW, pix = i % HW;
    float a0 = 0.0f, a1 = 0.0f, a2 = 0.0f;
#pragma unroll
    for (int c = 0; c < 16; c++) {
        float v = __ldg(in + (long long)(b * 16 + c) * HW + pix);
        a0 = fmaf(v, w[c * 3 + 0], a0);
        a1 = fmaf(v, w[c * 3 + 1], a1);
        a2 = fmaf(v, w[c * 3 + 2], a2);
    }
    out[o] = a0; out[o + 1] = a1; out[o + 2] = a2;
}

// CHW [B,32,HW] -> NHWC [B,HW,32]
__global__ void k_tr_c2(const float* __restrict__ in, float* __restrict__ outp, int HW) {
    __shared__ float t[32][33];
    int b = blockIdx.y;
    int px0 = blockIdx.x * 32;
    int tx = threadIdx.x, ty = threadIdx.y;
#pragma unroll
    for (int k = 0; k < 4; k++) {
        int c = ty + k * 8;
        t[c][tx] = in[(long long)(b * 32 + c) * HW + px0 + tx];
    }
    __syncthreads();
#pragma unroll
    for (int k = 0; k < 4; k++) {
        int pl = ty + k * 8;
        outp[((long long)b * HW + px0 + pl) * 32 + tx] = t[tx][pl];
    }
}

// ---------------------------------------------------------------------------
static inline unsigned grid_for(long long n) { return (unsigned)((n + 255) / 256); }

static inline size_t conv_smem_bytes(int W, int cgt) {
    int R = PX / W + 2;
    return (size_t)(2 * cgt * 9 * CO + 2 * cgt * R * (W + 8)) * sizeof(float);
}

extern "C" void kernel_launch(void* const* d_in, const int* in_sizes, int n_in,
                              void* d_out, int out_size) {
    (void)in_sizes; (void)n_in; (void)out_size;

    const float* x      = (const float*)d_in[0];
    const int*   mask   = (const int*)d_in[1];
    const float* w_ds1  = (const float*)d_in[2];
    const float* w_ds2  = (const float*)d_in[3];
    const float* w_ds3  = (const float*)d_in[4];
    const float* w_ds4  = (const float*)d_in[5];
    const float* w_brdg = (const float*)d_in[6];
    const float* wt4    = (const float*)d_in[7];
    const float* w_us4  = (const float*)d_in[8];
    const float* wt3    = (const float*)d_in[9];
    const float* w_us3  = (const float*)d_in[10];
    const float* wt2    = (const float*)d_in[11];
    const float* w_us2  = (const float*)d_in[12];
    const float* wt1    = (const float*)d_in[13];
    const float* w_us1  = (const float*)d_in[14];
    const float* w_out  = (const float*)d_in[15];

    float* out_final = (float*)d_out;                                    // [2,1024,1024,3]
    float* c2_out    = (float*)d_out + (long long)NB * 1024 * 1024 * 3;  // [2,512,512,32]

    float *c1, *p1, *c2, *p2, *c3, *p3, *c4, *p4, *br, *u4, *r4, *u3, *r3, *u2, *r2, *u1, *r1;
    unsigned char *m0, *m1, *m2, *m3, *m4, *mc4, *mc3, *mc2, *mc1;
    cudaGetSymbolAddress((void**)&c1, g_c1);
    cudaGetSymbolAddress((void**)&p1, g_p1);
    cudaGetSymbolAddress((void**)&c2, g_c2);
    cudaGetSymbolAddress((void**)&p2, g_p2);
    cudaGetSymbolAddress((void**)&c3, g_c3);
    cudaGetSymbolAddress((void**)&p3, g_p3);
    cudaGetSymbolAddress((void**)&c4, g_c4);
    cudaGetSymbolAddress((void**)&p4, g_p4);
    cudaGetSymbolAddress((void**)&br, g_br);
    cudaGetSymbolAddress((void**)&u4, g_u4);
    cudaGetSymbolAddress((void**)&r4, g_r4);
    cudaGetSymbolAddress((void**)&u3, g_u3);
    cudaGetSymbolAddress((void**)&r3, g_r3);
    cudaGetSymbolAddress((void**)&u2, g_u2);
    cudaGetSymbolAddress((void**)&r2, g_r2);
    cudaGetSymbolAddress((void**)&u1, g_u1);
    cudaGetSymbolAddress((void**)&r1, g_r1);
    cudaGetSymbolAddress((void**)&m0, g_m0);
    cudaGetSymbolAddress((void**)&m1, g_m1);
    cudaGetSymbolAddress((void**)&m2, g_m2);
    cudaGetSymbolAddress((void**)&m3, g_m3);
    cudaGetSymbolAddress((void**)&m4, g_m4);
    cudaGetSymbolAddress((void**)&mc4, g_mc4);
    cudaGetSymbolAddress((void**)&mc3, g_mc3);
    cudaGetSymbolAddress((void**)&mc2, g_mc2);
    cudaGetSymbolAddress((void**)&mc1, g_mc1);

    cudaFuncSetAttribute(conv3_smem<4, 2>, cudaFuncAttributeMaxDynamicSharedMemorySize,
                         (int)conv_smem_bytes(1024, 4) + 256);
    cudaFuncSetAttribute(conv3_smem<8, 3>, cudaFuncAttributeMaxDynamicSharedMemorySize,
                         (int)conv_smem_bytes(256, 8) + 256);

    const int TB = 256;
    long long n;

    // --- encoder (init fused into first conv) ---
    conv3_c1<<<dim3(1024, 1, NB), TB>>>(x, mask, w_ds1, m0, c1);

    n = (long long)NB * 16 * 512 * 512 / 4;
    k_pool4<<<grid_for(n), TB>>>(c1, m0, p1, m1, NB, 16, 512, 512);

    conv3_smem<4, 2><<<dim3(256, 2, NB), TB, conv_smem_bytes(512, 4)>>>(
        p1, nullptr, 16, 0, w_ds2, m1, c2, 512, 512, 9, 32);

    n = (long long)NB * 32 * 256 * 256 / 4;
    k_pool4<<<grid_for(n), TB>>>(c2, m1, p2, m2, NB, 32, 256, 256);

    conv3_smem<8, 3><<<dim3(64, 4, NB), TB, conv_smem_bytes(256, 8)>>>(
        p2, nullptr, 32, 0, w_ds3, m2, c3, 256, 256, 8, 64);

    n = (long long)NB * 64 * 128 * 128 / 4;
    k_pool4<<<grid_for(n), TB>>>(c3, m2, p3, m3, NB, 64, 128, 128);

    conv3_smem<8, 3><<<dim3(16, 8, NB), TB, conv_smem_bytes(128, 8)>>>(
        p3, nullptr, 64, 0, w_ds4, m3, c4, 128, 128, 7, 128);

    n = (long long)NB * 128 * 64 * 64 / 4;
    k_pool4<<<grid_for(n), TB>>>(c4, m3, p4, m4, NB, 128, 64, 64);

    // --- bridge ---
    conv3_smem<8, 3><<<dim3(4, 16, NB), TB, conv_smem_bytes(64, 8)>>>(
        p4, nullptr, 128, 0, w_brdg, m4, br, 64, 64, 6, 256);

    // --- decoder 4 ---
    tconv_chw<<<dim3(8, 16, NB), TB>>>(br, wt4, u4, 64, 64, 256, 128);
    n = (long long)NB * 128 * 128 / 4;
    k_mc4<<<grid_for(n), TB>>>(m4, m3, mc4, NB, 128, 128);
    conv3_smem<8, 3><<<dim3(16, 8, NB), TB, conv_smem_bytes(128, 8)>>>(
        u4, c4, 128, 128, w_us4, mc4, r4, 128, 128, 7, 128);

    // --- decoder 3 ---
    tconv_chw<<<dim3(32, 8, NB), TB>>>(r4, wt3, u3, 128, 128, 128, 64);
    n = (long long)NB * 256 * 256 / 4;
    k_mc4<<<grid_for(n), TB>>>(mc4, m2, mc3, NB, 256, 256);
    conv3_smem<8, 3><<<dim3(64, 4, NB), TB, conv_smem_bytes(256, 8)>>>(
        u3, c3, 64, 64, w_us3, mc3, r3, 256, 256, 8, 64);

    // --- decoder 2 ---
    tconv_chw<<<dim3(128, 4, NB), TB>>>(r3, wt2, u2, 256, 256, 64, 32);
    n = (long long)NB * 512 * 512 / 4;
    k_mc4<<<grid_for(n), TB>>>(mc3, m1, mc2, NB, 512, 512);
    conv3_smem<4, 2><<<dim3(256, 2, NB), TB, conv_smem_bytes(512, 4)>>>(
        u2, c2, 32, 32, w_us2, mc2, r2, 512, 512, 9, 32);

    // --- decoder 1 ---
    tconv_chw<<<dim3(512, 2, NB), TB>>>(r2, wt1, u1, 512, 512, 32, 16);
    n = (long long)NB * 1024 * 1024 / 4;
    k_mc4<<<grid_for(n), TB>>>(mc2, m0, mc1, NB, 1024, 1024);
    conv3_smem<4, 2><<<dim3(1024, 1, NB), TB, conv_smem_bytes(1024, 4)>>>(
        u1, c1, 16, 16, w_us1, mc1, r1, 1024, 1024, 10, 16);

    // --- outputs ---
    n = (long long)NB * 1024 * 1024;
    k_out1x1_chw<<<grid_for(n), TB>>>(r1, w_out, mc1, out_final, 1024 * 1024);

    k_tr_c2<<<dim3(512 * 512 / 32, NB), dim3(32, 8)>>>(c2, c2_out, 512 * 512);
}